// round 4
// baseline (speedup 1.0000x reference)
#include <cuda_runtime.h>
#include <cstdint>
#include <cstddef>

#define BB 64
#define WW 16
#define CC 64
#define TT 1024
#define DE 64
#define BW (BB*WW)           // 1024
#define WT (WW*TT)           // 16384
#define XR_SIZE ((size_t)BB*CC*WT)  // 67108864

__device__ float g_stat[BW*CC];
__device__ float g_Z[CC*DE];
__device__ float g_A2[CC*CC];

// ---------------- Kernel A: per-(b,w,c) robust stats ----------------
// stat = 0.5*(mean + energy) over T
__global__ void k_stats(const float* __restrict__ x) {
    int row  = blockIdx.x * 8 + (threadIdx.x >> 5);   // 0..65535
    int lane = threadIdx.x & 31;
    const float4* xv = reinterpret_cast<const float4*>(x + (size_t)row * TT);
    float s1 = 0.f, s2 = 0.f;
#pragma unroll
    for (int i = 0; i < 8; ++i) {
        float4 v = xv[lane + i * 32];
        s1 += v.x + v.y + v.z + v.w;
        s2 += v.x*v.x + v.y*v.y + v.z*v.z + v.w*v.w;
    }
#pragma unroll
    for (int off = 16; off; off >>= 1) {
        s1 += __shfl_down_sync(0xffffffffu, s1, off);
        s2 += __shfl_down_sync(0xffffffffu, s2, off);
    }
    if (lane == 0) g_stat[row] = (s1 + s2) * (0.5f / TT);
}

// ---------------- Kernel B: Z[c,d] = mean_{b,w} tanh(stat*Wp[d]) ----------------
__global__ void k_Z(const float* __restrict__ Wp) {
    __shared__ float sstat[BW];
    __shared__ float part[4][DE];
    int c = blockIdx.x;
    for (int i = threadIdx.x; i < BW; i += 256) sstat[i] = g_stat[i * CC + c];
    __syncthreads();
    int d = threadIdx.x & 63;
    int p = threadIdx.x >> 6;
    float w = Wp[d];
    float acc = 0.f;
    int i0 = p * 256;
    for (int i = i0; i < i0 + 256; ++i) acc += tanhf(sstat[i] * w);
    part[p][d] = acc;
    __syncthreads();
    if (threadIdx.x < DE) {
        g_Z[c * DE + threadIdx.x] =
            (part[0][threadIdx.x] + part[1][threadIdx.x] +
             part[2][threadIdx.x] + part[3][threadIdx.x]) * (1.0f / BW);
    }
}

// ---------------- threefry2x32 (JAX-exact) + gumbel ----------------
__device__ __forceinline__ uint32_t rotl32(uint32_t v, int d) {
    return (v << d) | (v >> (32 - d));
}

__device__ __forceinline__ void threefry_0_42(uint32_t x0, uint32_t x1,
                                              uint32_t& o0, uint32_t& o1) {
    const uint32_t k0 = 0u, k1 = 42u, k2 = 0u ^ 42u ^ 0x1BD11BDAu;
    x0 += k0; x1 += k1;
#define TF_R(r) { x0 += x1; x1 = rotl32(x1, r); x1 ^= x0; }
    TF_R(13) TF_R(15) TF_R(26) TF_R(6)   x0 += k1; x1 += k2 + 1u;
    TF_R(17) TF_R(29) TF_R(16) TF_R(24)  x0 += k2; x1 += k0 + 2u;
    TF_R(13) TF_R(15) TF_R(26) TF_R(6)   x0 += k0; x1 += k1 + 3u;
    TF_R(17) TF_R(29) TF_R(16) TF_R(24)  x0 += k1; x1 += k2 + 4u;
    TF_R(13) TF_R(15) TF_R(26) TF_R(6)   x0 += k2; x1 += k0 + 5u;
#undef TF_R
    o0 = x0; o1 = x1;
}

// JAX partitionable-threefry layout (default since JAX 0.4.36):
// element n gets counter pair (hi32(n), lo32(n)) = (0, n) for n < 2^32,
// and 32-bit random bits are the XOR of the two threefry output lanes:
//   bits[n] = out0 ^ out1 of threefry2x32(key, (0, n))
__device__ __forceinline__ float gumbel_at(int n) {
    uint32_t b0, b1;
    threefry_0_42(0u, (uint32_t)n, b0, b1);
    uint32_t bits = b0 ^ b1;
    float u = __uint_as_float((bits >> 9) | 0x3f800000u) - 1.0f;
    const float tiny = 1.17549435e-38f;
    float v = fmaxf(u, tiny);
    return -logf(-logf(v));
}

// ---------------- Kernel C: graph construction (single block, 256 thr) ----------------
__global__ void k_graph(const float* __restrict__ w1, const float* __restrict__ b1,
                        const float* __restrict__ w2, const float* __restrict__ b2,
                        const float* __restrict__ beta_p, const float* __restrict__ gamma_p,
                        const float* __restrict__ temp_p, float* __restrict__ outA) {
    __shared__ float sZ[CC * DE];   // Z, later reused: [0..63] holds d^{-1/2}
    __shared__ float sA[CC * CC];
    __shared__ float sB[CC * CC];   // temp; [0..63] holds sq early on
    int tid = threadIdx.x;

    for (int i = tid; i < CC * DE; i += 256) sZ[i] = g_Z[i];
    __syncthreads();

    if (tid < CC) {
        float s = 0.f;
        for (int d = 0; d < DE; ++d) { float z = sZ[tid * DE + d]; s += z * z; }
        sB[tid] = s;  // sq
    }
    __syncthreads();

    // D2 held in registers (16 elems per thread, contiguous), A = I
    float d2r[16];
    int e0 = tid * 16;
#pragma unroll
    for (int k = 0; k < 16; ++k) {
        int e = e0 + k; int i = e >> 6, j = e & 63;
        float dot = 0.f;
        for (int d = 0; d < DE; ++d) dot += sZ[i * DE + d] * sZ[j * DE + d];
        float v = sB[i] + sB[j] - 2.0f * dot;
        d2r[k] = fmaxf(v, 0.f) * 0.5f;
        sA[e] = (i == j) ? 1.f : 0.f;
    }
    __syncthreads();

    float lw1[16], lb1[16], lw2[16];
#pragma unroll
    for (int h = 0; h < 16; ++h) { lw1[h] = w1[h]; lb1[h] = b1[h]; lw2[h] = w2[h]; }
    float lb2 = b2[0];
    float beta = beta_p[0], gamma = gamma_p[0];
    const float inv_sqrt2 = 0.70710678118654752440f;

    for (int s = 0; s < 2; ++s) {
#pragma unroll
        for (int k = 0; k < 16; ++k) {
            int e = e0 + k;
            float a = sA[e] - 0.2f * d2r[k];
            float acc = lb2;
#pragma unroll
            for (int h = 0; h < 16; ++h) {
                float z = a * lw1[h] + lb1[h];
                float gel = 0.5f * z * (1.0f + erff(z * inv_sqrt2));  // exact gelu
                acc += gel * lw2[h];
            }
            // softplus = logaddexp(acc, 0)
            float delta = fmaxf(acc, 0.f) + log1pf(expf(-fabsf(acc)));
            sB[e] = a + beta * (delta * gamma);
        }
        __syncthreads();
#pragma unroll
        for (int k = 0; k < 16; ++k) {
            int e = e0 + k; int i = e >> 6, j = e & 63;
            float v = 0.5f * (sB[e] + sB[j * CC + i]);
            sA[e] = fmaxf(v, 0.f) + ((i == j) ? 1.f : 0.f);
        }
        __syncthreads();
    }

    // Gumbel top-k sparsification (k=16 per row); mask via argmax selection,
    // strict > keeps the lowest index on ties (matches lax.top_k).
    float invT = 1.0f / fmaxf(temp_p[0], 1e-6f);
    if (tid < CC) {
        int i = tid;
        float yv[64];
        for (int j = 0; j < CC; ++j)
            yv[j] = (sA[i * CC + j] + gumbel_at(i * CC + j)) * invT;
        unsigned long long m = 0ull;
        for (int k = 0; k < 16; ++k) {
            float best = -3.4e38f; int bi = 0;
            for (int j = 0; j < CC; ++j) {
                if (!((m >> j) & 1ull) && yv[j] > best) { best = yv[j]; bi = j; }
            }
            m |= 1ull << bi;
        }
        for (int j = 0; j < CC; ++j)
            sB[i * CC + j] = ((m >> j) & 1ull) ? sA[i * CC + j] : 0.f;
    }
    __syncthreads();

#pragma unroll
    for (int k = 0; k < 16; ++k) {
        int e = e0 + k; int i = e >> 6, j = e & 63;
        float v = 0.5f * (sB[e] + sB[j * CC + i]);
        sA[e] = fmaxf(v, 0.f) + ((i == j) ? 1.f : 0.f);
    }
    __syncthreads();

    if (tid < CC) {
        float s = 0.f;
        for (int j = 0; j < CC; ++j) s += sA[tid * CC + j];
        sZ[tid] = 1.0f / sqrtf(fmaxf(s, 1e-6f));   // d^{-1/2}
    }
    __syncthreads();

#pragma unroll
    for (int k = 0; k < 16; ++k) {
        int e = e0 + k; int i = e >> 6, j = e & 63;
        float v = (sZ[i] * sA[e]) * sZ[j];
        sB[e] = v + ((i == j) ? 1.f : 0.f);        // final A
    }
    __syncthreads();

    // emit A, and A2 = A@A for K_PROP=2 propagation
#pragma unroll
    for (int k = 0; k < 16; ++k) {
        int e = e0 + k;
        if (outA) outA[e] = sB[e];
        int i = e >> 6, j = e & 63;
        float acc = 0.f;
        for (int q = 0; q < CC; ++q) acc += sB[i * CC + q] * sB[q * CC + j];
        g_A2[e] = acc;
    }
}

// ---------------- Kernel D: out[b,c,w*T+t] = sum_j A2[c,j] * x[b,w,j,t] ----------------
__global__ __launch_bounds__(256, 4) void k_prop(const float* __restrict__ x,
                                                 float* __restrict__ out) {
    __shared__ float A2s[CC * CC];      // A2s[j*64+c] = A2[c][j] (transposed)
    __shared__ float xs[64 * 128];      // x tile: 64 channels x 128 t
    int bw  = blockIdx.y;               // 0..1023
    int tch = blockIdx.x;               // 0..7 (128-wide t chunks)
    int b = bw >> 4, w = bw & 15;
    int tid = threadIdx.x;

#pragma unroll
    for (int r = 0; r < 16; ++r) {
        int idx = tid + r * 256;
        int j = idx >> 6, c = idx & 63;
        A2s[idx] = g_A2[c * CC + j];
    }
#pragma unroll
    for (int r = 0; r < 8; ++r) {
        int lin = tid + r * 256;
        int j = lin >> 5, q = lin & 31;
        float4 v = reinterpret_cast<const float4*>(x)[
            (((size_t)bw * CC + j) * TT + (size_t)tch * 128) / 4 + q];
        *reinterpret_cast<float4*>(&xs[j * 128 + q * 4]) = v;
    }
    __syncthreads();

    int tc = tid & 31, ccg = tid >> 5;
    int c0 = ccg * 8, t0 = tc * 4;
    float acc[8][4];
#pragma unroll
    for (int u = 0; u < 8; ++u)
#pragma unroll
        for (int v = 0; v < 4; ++v) acc[u][v] = 0.f;

#pragma unroll 8
    for (int j = 0; j < CC; ++j) {
        float4 a0 = *reinterpret_cast<const float4*>(&A2s[j * 64 + c0]);     // broadcast
        float4 a1 = *reinterpret_cast<const float4*>(&A2s[j * 64 + c0 + 4]); // broadcast
        float4 xv = *reinterpret_cast<const float4*>(&xs[j * 128 + t0]);     // conflict-free
        float av[8] = {a0.x, a0.y, a0.z, a0.w, a1.x, a1.y, a1.z, a1.w};
        float xq[4] = {xv.x, xv.y, xv.z, xv.w};
#pragma unroll
        for (int u = 0; u < 8; ++u)
#pragma unroll
            for (int v = 0; v < 4; ++v) acc[u][v] += av[u] * xq[v];
    }

    size_t obase = (size_t)b * CC * WT + (size_t)w * TT + (size_t)tch * 128 + t0;
#pragma unroll
    for (int u = 0; u < 8; ++u) {
        float4 o = make_float4(acc[u][0], acc[u][1], acc[u][2], acc[u][3]);
        *reinterpret_cast<float4*>(out + obase + (size_t)(c0 + u) * WT) = o;
    }
}

// ---------------- launch ----------------
extern "C" void kernel_launch(void* const* d_in, const int* in_sizes, int n_in,
                              void* d_out, int out_size) {
    const float* x     = (const float*)d_in[0];
    const float* Wp    = (const float*)d_in[1];
    const float* w1    = (const float*)d_in[2];
    const float* b1    = (const float*)d_in[3];
    const float* w2    = (const float*)d_in[4];
    const float* b2    = (const float*)d_in[5];
    const float* beta  = (const float*)d_in[6];
    const float* gamma = (const float*)d_in[7];
    const float* temp  = (const float*)d_in[8];
    float* out = (float*)d_out;
    float* outA = ((size_t)out_size >= XR_SIZE + CC * CC) ? out + XR_SIZE : nullptr;

    k_stats<<<(BW * CC) / 8, 256>>>(x);
    k_Z<<<CC, 256>>>(Wp);
    k_graph<<<1, 256>>>(w1, b1, w2, b2, beta, gamma, temp, outA);
    dim3 g(8, BW);
    k_prop<<<g, 256>>>(x, out);
}

// round 5
// speedup vs baseline: 1.0037x; 1.0037x over previous
#include <cuda_runtime.h>
#include <cstdint>
#include <cstddef>

#define BB 64
#define WW 16
#define CC 64
#define TT 1024
#define DE 64
#define BW (BB*WW)           // 1024
#define WT (WW*TT)           // 16384
#define XR_SIZE ((size_t)BB*CC*WT)  // 67108864

__device__ float g_stat[BW*CC];
__device__ float g_Z[CC*DE];
__device__ float g_A2[CC*CC];

// ---------------- Kernel A: per-(b,w,c) robust stats ----------------
__global__ void k_stats(const float* __restrict__ x) {
    int row  = blockIdx.x * 8 + (threadIdx.x >> 5);   // 0..65535
    int lane = threadIdx.x & 31;
    const float4* xv = reinterpret_cast<const float4*>(x + (size_t)row * TT);
    float s1 = 0.f, s2 = 0.f;
#pragma unroll
    for (int i = 0; i < 8; ++i) {
        float4 v = xv[lane + i * 32];
        s1 += v.x + v.y + v.z + v.w;
        s2 += v.x*v.x + v.y*v.y + v.z*v.z + v.w*v.w;
    }
#pragma unroll
    for (int off = 16; off; off >>= 1) {
        s1 += __shfl_down_sync(0xffffffffu, s1, off);
        s2 += __shfl_down_sync(0xffffffffu, s2, off);
    }
    if (lane == 0) g_stat[row] = (s1 + s2) * (0.5f / TT);
}

// ---------------- Kernel B: Z[c,d] = mean_{b,w} tanh(stat*Wp[d]) ----------------
__global__ void k_Z(const float* __restrict__ Wp) {
    __shared__ float sstat[BW];
    __shared__ float part[4][DE];
    int c = blockIdx.x;
    for (int i = threadIdx.x; i < BW; i += 256) sstat[i] = g_stat[i * CC + c];
    __syncthreads();
    int d = threadIdx.x & 63;
    int p = threadIdx.x >> 6;
    float w = Wp[d];
    float acc = 0.f;
    int i0 = p * 256;
    for (int i = i0; i < i0 + 256; ++i) acc += tanhf(sstat[i] * w);
    part[p][d] = acc;
    __syncthreads();
    if (threadIdx.x < DE) {
        g_Z[c * DE + threadIdx.x] =
            (part[0][threadIdx.x] + part[1][threadIdx.x] +
             part[2][threadIdx.x] + part[3][threadIdx.x]) * (1.0f / BW);
    }
}

// ---------------- threefry2x32 (JAX partitionable) + gumbel ----------------
__device__ __forceinline__ uint32_t rotl32(uint32_t v, int d) {
    return (v << d) | (v >> (32 - d));
}

__device__ __forceinline__ void threefry_0_42(uint32_t x0, uint32_t x1,
                                              uint32_t& o0, uint32_t& o1) {
    const uint32_t k0 = 0u, k1 = 42u, k2 = 0u ^ 42u ^ 0x1BD11BDAu;
    x0 += k0; x1 += k1;
#define TF_R(r) { x0 += x1; x1 = rotl32(x1, r); x1 ^= x0; }
    TF_R(13) TF_R(15) TF_R(26) TF_R(6)   x0 += k1; x1 += k2 + 1u;
    TF_R(17) TF_R(29) TF_R(16) TF_R(24)  x0 += k2; x1 += k0 + 2u;
    TF_R(13) TF_R(15) TF_R(26) TF_R(6)   x0 += k0; x1 += k1 + 3u;
    TF_R(17) TF_R(29) TF_R(16) TF_R(24)  x0 += k1; x1 += k2 + 4u;
    TF_R(13) TF_R(15) TF_R(26) TF_R(6)   x0 += k2; x1 += k0 + 5u;
#undef TF_R
    o0 = x0; o1 = x1;
}

__device__ __forceinline__ float gumbel_at(int n) {
    uint32_t b0, b1;
    threefry_0_42(0u, (uint32_t)n, b0, b1);
    uint32_t bits = b0 ^ b1;
    float u = __uint_as_float((bits >> 9) | 0x3f800000u) - 1.0f;
    const float tiny = 1.17549435e-38f;
    float v = fmaxf(u, tiny);
    return -logf(-logf(v));
}

// ---------------- Kernel C: graph construction (single block, 256 thr) ----------------
__global__ void k_graph(const float* __restrict__ w1, const float* __restrict__ b1,
                        const float* __restrict__ w2, const float* __restrict__ b2,
                        const float* __restrict__ beta_p, const float* __restrict__ gamma_p,
                        const float* __restrict__ temp_p, float* __restrict__ outA) {
    __shared__ float sZ[CC * DE];
    __shared__ float sA[CC * CC];
    __shared__ float sB[CC * CC];
    int tid = threadIdx.x;

    for (int i = tid; i < CC * DE; i += 256) sZ[i] = g_Z[i];
    __syncthreads();

    if (tid < CC) {
        float s = 0.f;
        for (int d = 0; d < DE; ++d) { float z = sZ[tid * DE + d]; s += z * z; }
        sB[tid] = s;  // sq
    }
    __syncthreads();

    float d2r[16];
    int e0 = tid * 16;
#pragma unroll
    for (int k = 0; k < 16; ++k) {
        int e = e0 + k; int i = e >> 6, j = e & 63;
        float dot = 0.f;
        for (int d = 0; d < DE; ++d) dot += sZ[i * DE + d] * sZ[j * DE + d];
        float v = sB[i] + sB[j] - 2.0f * dot;
        d2r[k] = fmaxf(v, 0.f) * 0.5f;
        sA[e] = (i == j) ? 1.f : 0.f;
    }
    __syncthreads();

    float lw1[16], lb1[16], lw2[16];
#pragma unroll
    for (int h = 0; h < 16; ++h) { lw1[h] = w1[h]; lb1[h] = b1[h]; lw2[h] = w2[h]; }
    float lb2 = b2[0];
    float beta = beta_p[0], gamma = gamma_p[0];
    const float inv_sqrt2 = 0.70710678118654752440f;

    for (int s = 0; s < 2; ++s) {
#pragma unroll
        for (int k = 0; k < 16; ++k) {
            int e = e0 + k;
            float a = sA[e] - 0.2f * d2r[k];
            float acc = lb2;
#pragma unroll
            for (int h = 0; h < 16; ++h) {
                float z = a * lw1[h] + lb1[h];
                float gel = 0.5f * z * (1.0f + erff(z * inv_sqrt2));
                acc += gel * lw2[h];
            }
            float delta = fmaxf(acc, 0.f) + log1pf(expf(-fabsf(acc)));
            sB[e] = a + beta * (delta * gamma);
        }
        __syncthreads();
#pragma unroll
        for (int k = 0; k < 16; ++k) {
            int e = e0 + k; int i = e >> 6, j = e & 63;
            float v = 0.5f * (sB[e] + sB[j * CC + i]);
            sA[e] = fmaxf(v, 0.f) + ((i == j) ? 1.f : 0.f);
        }
        __syncthreads();
    }

    float invT = 1.0f / fmaxf(temp_p[0], 1e-6f);
    if (tid < CC) {
        int i = tid;
        float yv[64];
        for (int j = 0; j < CC; ++j)
            yv[j] = (sA[i * CC + j] + gumbel_at(i * CC + j)) * invT;
        unsigned long long m = 0ull;
        for (int k = 0; k < 16; ++k) {
            float best = -3.4e38f; int bi = 0;
            for (int j = 0; j < CC; ++j) {
                if (!((m >> j) & 1ull) && yv[j] > best) { best = yv[j]; bi = j; }
            }
            m |= 1ull << bi;
        }
        for (int j = 0; j < CC; ++j)
            sB[i * CC + j] = ((m >> j) & 1ull) ? sA[i * CC + j] : 0.f;
    }
    __syncthreads();

#pragma unroll
    for (int k = 0; k < 16; ++k) {
        int e = e0 + k; int i = e >> 6, j = e & 63;
        float v = 0.5f * (sB[e] + sB[j * CC + i]);
        sA[e] = fmaxf(v, 0.f) + ((i == j) ? 1.f : 0.f);
    }
    __syncthreads();

    if (tid < CC) {
        float s = 0.f;
        for (int j = 0; j < CC; ++j) s += sA[tid * CC + j];
        sZ[tid] = 1.0f / sqrtf(fmaxf(s, 1e-6f));
    }
    __syncthreads();

#pragma unroll
    for (int k = 0; k < 16; ++k) {
        int e = e0 + k; int i = e >> 6, j = e & 63;
        float v = (sZ[i] * sA[e]) * sZ[j];
        sB[e] = v + ((i == j) ? 1.f : 0.f);        // final A
    }
    __syncthreads();

#pragma unroll
    for (int k = 0; k < 16; ++k) {
        int e = e0 + k;
        if (outA) outA[e] = sB[e];
        int i = e >> 6, j = e & 63;
        float acc = 0.f;
        for (int q = 0; q < CC; ++q) acc += sB[i * CC + q] * sB[q * CC + j];
        g_A2[e] = acc;
    }
}

// ---------------- packed f32x2 helpers ----------------
__device__ __forceinline__ unsigned long long f32x2_pack_dup(float v) {
    unsigned long long r;
    asm("mov.b64 %0, {%1, %1};" : "=l"(r) : "f"(v));
    return r;
}
__device__ __forceinline__ void f32x2_fma(unsigned long long& d,
                                          unsigned long long a,
                                          unsigned long long b) {
    asm("fma.rn.f32x2 %0, %1, %2, %0;" : "+l"(d) : "l"(a), "l"(b));
}
__device__ __forceinline__ void f32x2_unpack(float& lo, float& hi, unsigned long long v) {
    asm("mov.b64 {%0, %1}, %2;" : "=f"(lo), "=f"(hi) : "l"(v));
}

// ---------------- Kernel D: out[b,c,w*T+t] = sum_j A2[c,j] * x[b,w,j,t] ----------------
// Packed over the c dimension: A2 pairs come free from LDS.128; x is duplicated.
__global__ __launch_bounds__(256, 3) void k_prop(const float* __restrict__ x,
                                                 float* __restrict__ out) {
    __shared__ float A2s[CC * CC];      // A2s[j*64+c] = A2[c][j] (transposed)
    __shared__ float xs[64 * 128];      // x tile: 64 channels x 128 t
    int bw  = blockIdx.y;               // 0..1023
    int tch = blockIdx.x;               // 0..7 (128-wide t chunks)
    int b = bw >> 4, w = bw & 15;
    int tid = threadIdx.x;

#pragma unroll
    for (int r = 0; r < 16; ++r) {
        int idx = tid + r * 256;
        int j = idx >> 6, c = idx & 63;
        A2s[idx] = g_A2[c * CC + j];
    }
#pragma unroll
    for (int r = 0; r < 8; ++r) {
        int lin = tid + r * 256;
        int j = lin >> 5, q = lin & 31;
        float4 v = reinterpret_cast<const float4*>(x)[
            (((size_t)bw * CC + j) * TT + (size_t)tch * 128) / 4 + q];
        *reinterpret_cast<float4*>(&xs[j * 128 + q * 4]) = v;
    }
    __syncthreads();

    int tc = tid & 31, ccg = tid >> 5;
    int c0 = ccg * 8, t0 = tc * 4;

    // acc[u2][v]: c-pair (c0+2u2, c0+2u2+1) at time t0+v, packed f32x2
    unsigned long long acc[4][4];
#pragma unroll
    for (int u = 0; u < 4; ++u)
#pragma unroll
        for (int v = 0; v < 4; ++v) acc[u][v] = 0ull;

#pragma unroll 4
    for (int j = 0; j < CC; ++j) {
        // 2x LDS.128 broadcast; little-endian: .x of ulonglong2 = (c0, c0+1)
        ulonglong2 p0 = *reinterpret_cast<const ulonglong2*>(&A2s[j * 64 + c0]);
        ulonglong2 p1 = *reinterpret_cast<const ulonglong2*>(&A2s[j * 64 + c0 + 4]);
        float4 xv = *reinterpret_cast<const float4*>(&xs[j * 128 + t0]);   // conflict-free
        unsigned long long au[4] = {p0.x, p0.y, p1.x, p1.y};
        unsigned long long xd[4] = {f32x2_pack_dup(xv.x), f32x2_pack_dup(xv.y),
                                    f32x2_pack_dup(xv.z), f32x2_pack_dup(xv.w)};
#pragma unroll
        for (int u = 0; u < 4; ++u)
#pragma unroll
            for (int v = 0; v < 4; ++v) f32x2_fma(acc[u][v], au[u], xd[v]);
    }

    size_t obase = (size_t)b * CC * WT + (size_t)w * TT + (size_t)tch * 128 + t0;
#pragma unroll
    for (int u = 0; u < 4; ++u) {
        float e0f, o0f, e1f, o1f, e2f, o2f, e3f, o3f;
        f32x2_unpack(e0f, o0f, acc[u][0]);
        f32x2_unpack(e1f, o1f, acc[u][1]);
        f32x2_unpack(e2f, o2f, acc[u][2]);
        f32x2_unpack(e3f, o3f, acc[u][3]);
        int ce = c0 + 2 * u, co = ce + 1;
        *reinterpret_cast<float4*>(out + obase + (size_t)ce * WT) =
            make_float4(e0f, e1f, e2f, e3f);
        *reinterpret_cast<float4*>(out + obase + (size_t)co * WT) =
            make_float4(o0f, o1f, o2f, o3f);
    }
}

// ---------------- launch ----------------
extern "C" void kernel_launch(void* const* d_in, const int* in_sizes, int n_in,
                              void* d_out, int out_size) {
    const float* x     = (const float*)d_in[0];
    const float* Wp    = (const float*)d_in[1];
    const float* w1    = (const float*)d_in[2];
    const float* b1    = (const float*)d_in[3];
    const float* w2    = (const float*)d_in[4];
    const float* b2    = (const float*)d_in[5];
    const float* beta  = (const float*)d_in[6];
    const float* gamma = (const float*)d_in[7];
    const float* temp  = (const float*)d_in[8];
    float* out = (float*)d_out;
    float* outA = ((size_t)out_size >= XR_SIZE + CC * CC) ? out + XR_SIZE : nullptr;

    k_stats<<<(BW * CC) / 8, 256>>>(x);
    k_Z<<<CC, 256>>>(Wp);
    k_graph<<<1, 256>>>(w1, b1, w2, b2, beta, gamma, temp, outA);
    dim3 g(8, BW);
    k_prop<<<g, 256>>>(x, out);
}

// round 7
// speedup vs baseline: 1.0290x; 1.0252x over previous
#include <cuda_runtime.h>
#include <cstdint>
#include <cstddef>

#define BB 64
#define WW 16
#define CC 64
#define TT 1024
#define DE 64
#define BW (BB*WW)           // 1024
#define WT (WW*TT)           // 16384
#define XR_SIZE ((size_t)BB*CC*WT)  // 67108864

__device__ float g_stat[BW*CC];
__device__ float g_Zpart[4][CC*DE];
__device__ float g_A2[CC*CC];

// ---------------- Kernel A: per-(b,w,c) robust stats ----------------
__global__ void k_stats(const float* __restrict__ x) {
    int row  = blockIdx.x * 8 + (threadIdx.x >> 5);   // 0..65535
    int lane = threadIdx.x & 31;
    const float4* xv = reinterpret_cast<const float4*>(x + (size_t)row * TT);
    float s1 = 0.f, s2 = 0.f;
#pragma unroll
    for (int i = 0; i < 8; ++i) {
        float4 v = xv[lane + i * 32];
        s1 += v.x + v.y + v.z + v.w;
        s2 += v.x*v.x + v.y*v.y + v.z*v.z + v.w*v.w;
    }
#pragma unroll
    for (int off = 16; off; off >>= 1) {
        s1 += __shfl_down_sync(0xffffffffu, s1, off);
        s2 += __shfl_down_sync(0xffffffffu, s2, off);
    }
    if (lane == 0) g_stat[row] = (s1 + s2) * (0.5f / TT);
}

// ---------------- Kernel B: partial Z over i-quarters ----------------
// g_Zpart[pr][c*DE+d] = sum_{i in quarter pr} tanh(stat[i,c] * Wp[d])
__global__ void k_Z(const float* __restrict__ Wp) {
    __shared__ float sstat[256];
    __shared__ float part[4][DE];
    int c = blockIdx.x;
    int pr = blockIdx.y;
    int base = pr * 256;
    if (threadIdx.x < 256) {
        if (threadIdx.x < 256) sstat[threadIdx.x] = g_stat[(base + threadIdx.x) * CC + c];
    }
    __syncthreads();
    int d = threadIdx.x & 63;
    int p = threadIdx.x >> 6;
    float w = Wp[d];
    float acc = 0.f;
    int i0 = p * 64;
    for (int i = i0; i < i0 + 64; ++i) acc += tanhf(sstat[i] * w);
    part[p][d] = acc;
    __syncthreads();
    if (threadIdx.x < DE) {
        g_Zpart[pr][c * DE + threadIdx.x] =
            part[0][threadIdx.x] + part[1][threadIdx.x] +
            part[2][threadIdx.x] + part[3][threadIdx.x];
    }
}

// ---------------- threefry2x32 (JAX partitionable) + gumbel ----------------
__device__ __forceinline__ uint32_t rotl32(uint32_t v, int d) {
    return (v << d) | (v >> (32 - d));
}

__device__ __forceinline__ void threefry_0_42(uint32_t x0, uint32_t x1,
                                              uint32_t& o0, uint32_t& o1) {
    const uint32_t k0 = 0u, k1 = 42u, k2 = 0u ^ 42u ^ 0x1BD11BDAu;
    x0 += k0; x1 += k1;
#define TF_R(r) { x0 += x1; x1 = rotl32(x1, r); x1 ^= x0; }
    TF_R(13) TF_R(15) TF_R(26) TF_R(6)   x0 += k1; x1 += k2 + 1u;
    TF_R(17) TF_R(29) TF_R(16) TF_R(24)  x0 += k2; x1 += k0 + 2u;
    TF_R(13) TF_R(15) TF_R(26) TF_R(6)   x0 += k0; x1 += k1 + 3u;
    TF_R(17) TF_R(29) TF_R(16) TF_R(24)  x0 += k1; x1 += k2 + 4u;
    TF_R(13) TF_R(15) TF_R(26) TF_R(6)   x0 += k2; x1 += k0 + 5u;
#undef TF_R
    o0 = x0; o1 = x1;
}

__device__ __forceinline__ float gumbel_at(int n) {
    uint32_t b0, b1;
    threefry_0_42(0u, (uint32_t)n, b0, b1);
    uint32_t bits = b0 ^ b1;
    float u = __uint_as_float((bits >> 9) | 0x3f800000u) - 1.0f;
    const float tiny = 1.17549435e-38f;
    float v = fmaxf(u, tiny);
    return -logf(-logf(v));
}

// ---------------- Kernel C: graph construction (single block, 256 thr) ----------------
__global__ void k_graph(const float* __restrict__ w1, const float* __restrict__ b1,
                        const float* __restrict__ w2, const float* __restrict__ b2,
                        const float* __restrict__ beta_p, const float* __restrict__ gamma_p,
                        const float* __restrict__ temp_p, float* __restrict__ outA) {
    __shared__ float sZ[CC * DE];
    __shared__ float sA[CC * CC];
    __shared__ float sB[CC * CC];
    int tid = threadIdx.x;

    for (int i = tid; i < CC * DE; i += 256)
        sZ[i] = (g_Zpart[0][i] + g_Zpart[1][i] + g_Zpart[2][i] + g_Zpart[3][i])
                * (1.0f / BW);
    __syncthreads();

    if (tid < CC) {
        float s = 0.f;
        for (int d = 0; d < DE; ++d) { float z = sZ[tid * DE + d]; s += z * z; }
        sB[tid] = s;  // sq
    }
    __syncthreads();

    float d2r[16];
    int e0 = tid * 16;
#pragma unroll
    for (int k = 0; k < 16; ++k) {
        int e = e0 + k; int i = e >> 6, j = e & 63;
        float dot = 0.f;
        for (int d = 0; d < DE; ++d) dot += sZ[i * DE + d] * sZ[j * DE + d];
        float v = sB[i] + sB[j] - 2.0f * dot;
        d2r[k] = fmaxf(v, 0.f) * 0.5f;
        sA[e] = (i == j) ? 1.f : 0.f;
    }
    __syncthreads();

    float lw1[16], lb1[16], lw2[16];
#pragma unroll
    for (int h = 0; h < 16; ++h) { lw1[h] = w1[h]; lb1[h] = b1[h]; lw2[h] = w2[h]; }
    float lb2 = b2[0];
    float beta = beta_p[0], gamma = gamma_p[0];
    const float inv_sqrt2 = 0.70710678118654752440f;

    for (int s = 0; s < 2; ++s) {
#pragma unroll
        for (int k = 0; k < 16; ++k) {
            int e = e0 + k;
            float a = sA[e] - 0.2f * d2r[k];
            float acc = lb2;
#pragma unroll
            for (int h = 0; h < 16; ++h) {
                float z = a * lw1[h] + lb1[h];
                float gel = 0.5f * z * (1.0f + erff(z * inv_sqrt2));
                acc += gel * lw2[h];
            }
            float delta = fmaxf(acc, 0.f) + log1pf(expf(-fabsf(acc)));
            sB[e] = a + beta * (delta * gamma);
        }
        __syncthreads();
#pragma unroll
        for (int k = 0; k < 16; ++k) {
            int e = e0 + k; int i = e >> 6, j = e & 63;
            float v = 0.5f * (sB[e] + sB[j * CC + i]);
            sA[e] = fmaxf(v, 0.f) + ((i == j) ? 1.f : 0.f);
        }
        __syncthreads();
    }

    float invT = 1.0f / fmaxf(temp_p[0], 1e-6f);
    if (tid < CC) {
        int i = tid;
        float yv[64];
        for (int j = 0; j < CC; ++j)
            yv[j] = (sA[i * CC + j] + gumbel_at(i * CC + j)) * invT;
        unsigned long long m = 0ull;
        for (int k = 0; k < 16; ++k) {
            float best = -3.4e38f; int bi = 0;
            for (int j = 0; j < CC; ++j) {
                if (!((m >> j) & 1ull) && yv[j] > best) { best = yv[j]; bi = j; }
            }
            m |= 1ull << bi;
        }
        for (int j = 0; j < CC; ++j)
            sB[i * CC + j] = ((m >> j) & 1ull) ? sA[i * CC + j] : 0.f;
    }
    __syncthreads();

#pragma unroll
    for (int k = 0; k < 16; ++k) {
        int e = e0 + k; int i = e >> 6, j = e & 63;
        float v = 0.5f * (sB[e] + sB[j * CC + i]);
        sA[e] = fmaxf(v, 0.f) + ((i == j) ? 1.f : 0.f);
    }
    __syncthreads();

    if (tid < CC) {
        float s = 0.f;
        for (int j = 0; j < CC; ++j) s += sA[tid * CC + j];
        sZ[tid] = 1.0f / sqrtf(fmaxf(s, 1e-6f));
    }
    __syncthreads();

#pragma unroll
    for (int k = 0; k < 16; ++k) {
        int e = e0 + k; int i = e >> 6, j = e & 63;
        float v = (sZ[i] * sA[e]) * sZ[j];
        sB[e] = v + ((i == j) ? 1.f : 0.f);        // final A
    }
    __syncthreads();

#pragma unroll
    for (int k = 0; k < 16; ++k) {
        int e = e0 + k;
        if (outA) outA[e] = sB[e];
        int i = e >> 6, j = e & 63;
        float acc = 0.f;
        for (int q = 0; q < CC; ++q) acc += sB[i * CC + q] * sB[q * CC + j];
        g_A2[e] = acc;
    }
}

// ---------------- packed f32x2 helpers ----------------
__device__ __forceinline__ unsigned long long f32x2_pack_dup(float v) {
    unsigned long long r;
    asm("mov.b64 %0, {%1, %1};" : "=l"(r) : "f"(v));
    return r;
}
__device__ __forceinline__ void f32x2_fma(unsigned long long& d,
                                          unsigned long long a,
                                          unsigned long long b) {
    asm("fma.rn.f32x2 %0, %1, %2, %0;" : "+l"(d) : "l"(a), "l"(b));
}
__device__ __forceinline__ void f32x2_unpack(float& lo, float& hi, unsigned long long v) {
    asm("mov.b64 {%0, %1}, %2;" : "=f"(lo), "=f"(hi) : "l"(v));
}

// ---------------- Kernel D: out[b,c,w*T+t] = sum_j A2[c,j] * x[b,w,j,t] ----------------
// 128 threads / 4 warps; warp wi owns c-group c0=wi*16, lanes own t0=lane*4.
// Per thread: 16c x 4t (8 f32x2 c-pairs). A2 loads are warp-broadcast (cheap wf);
// x LDS traffic amortized over 16 c per thread (2x previous density).
__global__ __launch_bounds__(128, 4) void k_prop(const float* __restrict__ x,
                                                 float* __restrict__ out) {
    __shared__ float A2s[CC * CC];      // A2s[j*64+c] = A2[c][j] (transposed)
    __shared__ float xs[64 * 128];      // x tile: 64 channels x 128 t
    int bw  = blockIdx.y;               // 0..1023
    int tch = blockIdx.x;               // 0..7 (128-wide t chunks)
    int b = bw >> 4, w = bw & 15;
    int tid = threadIdx.x;

#pragma unroll
    for (int r = 0; r < 32; ++r) {
        int idx = tid + r * 128;
        int j = idx >> 6, c = idx & 63;
        A2s[idx] = g_A2[c * CC + j];
    }
#pragma unroll
    for (int r = 0; r < 16; ++r) {
        int lin = tid + r * 128;        // 0..2047 float4 slots
        int j = lin >> 5, q = lin & 31;
        float4 v = reinterpret_cast<const float4*>(x)[
            (((size_t)bw * CC + j) * TT + (size_t)tch * 128) / 4 + q];
        *reinterpret_cast<float4*>(&xs[j * 128 + q * 4]) = v;
    }
    __syncthreads();

    int lane = tid & 31, wi = tid >> 5;
    int c0 = wi * 16, t0 = lane * 4;

    // acc[u][v]: c-pair (c0+2u, c0+2u+1) at time t0+v, packed f32x2
    unsigned long long acc[8][4];
#pragma unroll
    for (int u = 0; u < 8; ++u)
#pragma unroll
        for (int v = 0; v < 4; ++v) acc[u][v] = 0ull;

#pragma unroll 2
    for (int j = 0; j < CC; ++j) {
        // 4x LDS.128 warp-broadcast of A2 pairs; little-endian .x = (c, c+1)
        ulonglong2 p0 = *reinterpret_cast<const ulonglong2*>(&A2s[j * 64 + c0]);
        ulonglong2 p1 = *reinterpret_cast<const ulonglong2*>(&A2s[j * 64 + c0 + 4]);
        ulonglong2 p2 = *reinterpret_cast<const ulonglong2*>(&A2s[j * 64 + c0 + 8]);
        ulonglong2 p3 = *reinterpret_cast<const ulonglong2*>(&A2s[j * 64 + c0 + 12]);
        float4 xv = *reinterpret_cast<const float4*>(&xs[j * 128 + t0]);   // conflict-free
        unsigned long long au[8] = {p0.x, p0.y, p1.x, p1.y, p2.x, p2.y, p3.x, p3.y};
        unsigned long long xd[4] = {f32x2_pack_dup(xv.x), f32x2_pack_dup(xv.y),
                                    f32x2_pack_dup(xv.z), f32x2_pack_dup(xv.w)};
#pragma unroll
        for (int u = 0; u < 8; ++u)
#pragma unroll
            for (int v = 0; v < 4; ++v) f32x2_fma(acc[u][v], au[u], xd[v]);
    }

    size_t obase = (size_t)b * CC * WT + (size_t)w * TT + (size_t)tch * 128 + t0;
#pragma unroll
    for (int u = 0; u < 8; ++u) {
        float e0f, o0f, e1f, o1f, e2f, o2f, e3f, o3f;
        f32x2_unpack(e0f, o0f, acc[u][0]);
        f32x2_unpack(e1f, o1f, acc[u][1]);
        f32x2_unpack(e2f, o2f, acc[u][2]);
        f32x2_unpack(e3f, o3f, acc[u][3]);
        int ce = c0 + 2 * u, co = ce + 1;
        *reinterpret_cast<float4*>(out + obase + (size_t)ce * WT) =
            make_float4(e0f, e1f, e2f, e3f);
        *reinterpret_cast<float4*>(out + obase + (size_t)co * WT) =
            make_float4(o0f, o1f, o2f, o3f);
    }
}

// ---------------- launch ----------------
extern "C" void kernel_launch(void* const* d_in, const int* in_sizes, int n_in,
                              void* d_out, int out_size) {
    const float* x     = (const float*)d_in[0];
    const float* Wp    = (const float*)d_in[1];
    const float* w1    = (const float*)d_in[2];
    const float* b1    = (const float*)d_in[3];
    const float* w2    = (const float*)d_in[4];
    const float* b2    = (const float*)d_in[5];
    const float* beta  = (const float*)d_in[6];
    const float* gamma = (const float*)d_in[7];
    const float* temp  = (const float*)d_in[8];
    float* out = (float*)d_out;
    float* outA = ((size_t)out_size >= XR_SIZE + CC * CC) ? out + XR_SIZE : nullptr;

    k_stats<<<(BW * CC) / 8, 256>>>(x);
    k_Z<<<dim3(CC, 4), 256>>>(Wp);
    k_graph<<<1, 256>>>(w1, b1, w2, b2, beta, gamma, temp, outA);
    dim3 g(8, BW);
    k_prop<<<g, 128>>>(x, out);
}

// round 9
// speedup vs baseline: 1.3485x; 1.3105x over previous
#include <cuda_runtime.h>
#include <cuda_bf16.h>
#include <cstdint>
#include <cstddef>

#define BB 64
#define WW 16
#define CC 64
#define TT 1024
#define DE 64
#define BW (BB*WW)           // 1024
#define WT (WW*TT)           // 16384
#define XR_SIZE ((size_t)BB*CC*WT)  // 67108864

__device__ float g_stat[BW*CC];
__device__ float g_Zpart[4][CC*DE];
__device__ __nv_bfloat16 g_A2h[CC*CC];
__device__ __nv_bfloat16 g_A2l[CC*CC];

// ---------------- Kernel A: per-(b,w,c) robust stats ----------------
__global__ void k_stats(const float* __restrict__ x) {
    int row  = blockIdx.x * 8 + (threadIdx.x >> 5);   // 0..65535
    int lane = threadIdx.x & 31;
    const float4* xv = reinterpret_cast<const float4*>(x + (size_t)row * TT);
    float s1 = 0.f, s2 = 0.f;
#pragma unroll
    for (int i = 0; i < 8; ++i) {
        float4 v = xv[lane + i * 32];
        s1 += v.x + v.y + v.z + v.w;
        s2 += v.x*v.x + v.y*v.y + v.z*v.z + v.w*v.w;
    }
#pragma unroll
    for (int off = 16; off; off >>= 1) {
        s1 += __shfl_down_sync(0xffffffffu, s1, off);
        s2 += __shfl_down_sync(0xffffffffu, s2, off);
    }
    if (lane == 0) g_stat[row] = (s1 + s2) * (0.5f / TT);
}

// ---------------- Kernel B: partial Z over i-quarters ----------------
__global__ void k_Z(const float* __restrict__ Wp) {
    __shared__ float sstat[256];
    __shared__ float part[4][DE];
    int c = blockIdx.x;
    int pr = blockIdx.y;
    int base = pr * 256;
    sstat[threadIdx.x] = g_stat[(base + threadIdx.x) * CC + c];
    __syncthreads();
    int d = threadIdx.x & 63;
    int p = threadIdx.x >> 6;
    float w = Wp[d];
    float acc = 0.f;
    int i0 = p * 64;
    for (int i = i0; i < i0 + 64; ++i) acc += tanhf(sstat[i] * w);
    part[p][d] = acc;
    __syncthreads();
    if (threadIdx.x < DE) {
        g_Zpart[pr][c * DE + threadIdx.x] =
            part[0][threadIdx.x] + part[1][threadIdx.x] +
            part[2][threadIdx.x] + part[3][threadIdx.x];
    }
}

// ---------------- threefry2x32 (JAX partitionable) + gumbel ----------------
__device__ __forceinline__ uint32_t rotl32(uint32_t v, int d) {
    return (v << d) | (v >> (32 - d));
}

__device__ __forceinline__ void threefry_0_42(uint32_t x0, uint32_t x1,
                                              uint32_t& o0, uint32_t& o1) {
    const uint32_t k0 = 0u, k1 = 42u, k2 = 0u ^ 42u ^ 0x1BD11BDAu;
    x0 += k0; x1 += k1;
#define TF_R(r) { x0 += x1; x1 = rotl32(x1, r); x1 ^= x0; }
    TF_R(13) TF_R(15) TF_R(26) TF_R(6)   x0 += k1; x1 += k2 + 1u;
    TF_R(17) TF_R(29) TF_R(16) TF_R(24)  x0 += k2; x1 += k0 + 2u;
    TF_R(13) TF_R(15) TF_R(26) TF_R(6)   x0 += k0; x1 += k1 + 3u;
    TF_R(17) TF_R(29) TF_R(16) TF_R(24)  x0 += k1; x1 += k2 + 4u;
    TF_R(13) TF_R(15) TF_R(26) TF_R(6)   x0 += k2; x1 += k0 + 5u;
#undef TF_R
    o0 = x0; o1 = x1;
}

__device__ __forceinline__ float gumbel_at(int n) {
    uint32_t b0, b1;
    threefry_0_42(0u, (uint32_t)n, b0, b1);
    uint32_t bits = b0 ^ b1;
    float u = __uint_as_float((bits >> 9) | 0x3f800000u) - 1.0f;
    const float tiny = 1.17549435e-38f;
    float v = fmaxf(u, tiny);
    return -logf(-logf(v));
}

// ---------------- Kernel C: graph construction (single block, 256 thr) ----------------
__global__ void k_graph(const float* __restrict__ w1, const float* __restrict__ b1,
                        const float* __restrict__ w2, const float* __restrict__ b2,
                        const float* __restrict__ beta_p, const float* __restrict__ gamma_p,
                        const float* __restrict__ temp_p, float* __restrict__ outA) {
    __shared__ float sZ[CC * DE];
    __shared__ float sA[CC * CC];
    __shared__ float sB[CC * CC];
    int tid = threadIdx.x;

    for (int i = tid; i < CC * DE; i += 256)
        sZ[i] = (g_Zpart[0][i] + g_Zpart[1][i] + g_Zpart[2][i] + g_Zpart[3][i])
                * (1.0f / BW);
    __syncthreads();

    if (tid < CC) {
        float s = 0.f;
        for (int d = 0; d < DE; ++d) { float z = sZ[tid * DE + d]; s += z * z; }
        sB[tid] = s;  // sq
    }
    __syncthreads();

    float d2r[16];
    int e0 = tid * 16;
#pragma unroll
    for (int k = 0; k < 16; ++k) {
        int e = e0 + k; int i = e >> 6, j = e & 63;
        float dot = 0.f;
        for (int d = 0; d < DE; ++d) dot += sZ[i * DE + d] * sZ[j * DE + d];
        float v = sB[i] + sB[j] - 2.0f * dot;
        d2r[k] = fmaxf(v, 0.f) * 0.5f;
        sA[e] = (i == j) ? 1.f : 0.f;
    }
    __syncthreads();

    float lw1[16], lb1[16], lw2[16];
#pragma unroll
    for (int h = 0; h < 16; ++h) { lw1[h] = w1[h]; lb1[h] = b1[h]; lw2[h] = w2[h]; }
    float lb2 = b2[0];
    float beta = beta_p[0], gamma = gamma_p[0];
    const float inv_sqrt2 = 0.70710678118654752440f;

    for (int s = 0; s < 2; ++s) {
#pragma unroll
        for (int k = 0; k < 16; ++k) {
            int e = e0 + k;
            float a = sA[e] - 0.2f * d2r[k];
            float acc = lb2;
#pragma unroll
            for (int h = 0; h < 16; ++h) {
                float z = a * lw1[h] + lb1[h];
                float gel = 0.5f * z * (1.0f + erff(z * inv_sqrt2));
                acc += gel * lw2[h];
            }
            float delta = fmaxf(acc, 0.f) + log1pf(expf(-fabsf(acc)));
            sB[e] = a + beta * (delta * gamma);
        }
        __syncthreads();
#pragma unroll
        for (int k = 0; k < 16; ++k) {
            int e = e0 + k; int i = e >> 6, j = e & 63;
            float v = 0.5f * (sB[e] + sB[j * CC + i]);
            sA[e] = fmaxf(v, 0.f) + ((i == j) ? 1.f : 0.f);
        }
        __syncthreads();
    }

    float invT = 1.0f / fmaxf(temp_p[0], 1e-6f);
    if (tid < CC) {
        int i = tid;
        float yv[64];
        for (int j = 0; j < CC; ++j)
            yv[j] = (sA[i * CC + j] + gumbel_at(i * CC + j)) * invT;
        unsigned long long m = 0ull;
        for (int k = 0; k < 16; ++k) {
            float best = -3.4e38f; int bi = 0;
            for (int j = 0; j < CC; ++j) {
                if (!((m >> j) & 1ull) && yv[j] > best) { best = yv[j]; bi = j; }
            }
            m |= 1ull << bi;
        }
        for (int j = 0; j < CC; ++j)
            sB[i * CC + j] = ((m >> j) & 1ull) ? sA[i * CC + j] : 0.f;
    }
    __syncthreads();

#pragma unroll
    for (int k = 0; k < 16; ++k) {
        int e = e0 + k; int i = e >> 6, j = e & 63;
        float v = 0.5f * (sB[e] + sB[j * CC + i]);
        sA[e] = fmaxf(v, 0.f) + ((i == j) ? 1.f : 0.f);
    }
    __syncthreads();

    if (tid < CC) {
        float s = 0.f;
        for (int j = 0; j < CC; ++j) s += sA[tid * CC + j];
        sZ[tid] = 1.0f / sqrtf(fmaxf(s, 1e-6f));
    }
    __syncthreads();

#pragma unroll
    for (int k = 0; k < 16; ++k) {
        int e = e0 + k; int i = e >> 6, j = e & 63;
        float v = (sZ[i] * sA[e]) * sZ[j];
        sB[e] = v + ((i == j) ? 1.f : 0.f);        // final A
    }
    __syncthreads();

    // emit A, and A2 = A@A (bf16 hi/lo split) for K_PROP=2 propagation
#pragma unroll
    for (int k = 0; k < 16; ++k) {
        int e = e0 + k;
        if (outA) outA[e] = sB[e];
        int i = e >> 6, j = e & 63;
        float acc = 0.f;
        for (int q = 0; q < CC; ++q) acc += sB[i * CC + q] * sB[q * CC + j];
        __nv_bfloat16 h = __float2bfloat16(acc);
        __nv_bfloat16 l = __float2bfloat16(acc - __bfloat162float(h));
        g_A2h[e] = h;
        g_A2l[e] = l;
    }
}

// ================== mma.sync bf16 helpers (sm_80+ PTX, compute_103-safe) ====
__device__ __forceinline__ uint32_t smem_u32(const void* p) {
    uint32_t a;
    asm("{ .reg .u64 t; cvta.to.shared.u64 t, %1; cvt.u32.u64 %0, t; }"
        : "=r"(a) : "l"(p));
    return a;
}

__device__ __forceinline__ void ldsm_x4_t(uint32_t& d0, uint32_t& d1,
                                          uint32_t& d2, uint32_t& d3,
                                          uint32_t addr) {
    asm volatile(
        "ldmatrix.sync.aligned.m8n8.x4.trans.shared.b16 {%0,%1,%2,%3}, [%4];"
        : "=r"(d0), "=r"(d1), "=r"(d2), "=r"(d3) : "r"(addr));
}

__device__ __forceinline__ void mma_bf16(float& d0, float& d1, float& d2, float& d3,
                                         uint32_t a0, uint32_t a1, uint32_t a2, uint32_t a3,
                                         uint32_t b0, uint32_t b1) {
    asm volatile(
        "mma.sync.aligned.m16n8k16.row.col.f32.bf16.bf16.f32 "
        "{%0,%1,%2,%3}, {%4,%5,%6,%7}, {%8,%9}, {%0,%1,%2,%3};"
        : "+f"(d0), "+f"(d1), "+f"(d2), "+f"(d3)
        : "r"(a0), "r"(a1), "r"(a2), "r"(a3), "r"(b0), "r"(b1));
}

__device__ __forceinline__ uint32_t pack2h(__nv_bfloat16 a, __nv_bfloat16 b) {
    return (uint32_t)__bfloat16_as_ushort(a) |
           ((uint32_t)__bfloat16_as_ushort(b) << 16);
}

// xt tile: [j=0..63][t=0..127] bf16, row = 256B, 16B-chunk XOR swizzle:
// byte(j, t) = j*256 + (((t>>3) ^ (j&7)) << 4) + (t&7)*2
__device__ __forceinline__ uint32_t xt_off(int j, int t) {
    return (uint32_t)(j * 256 + ((((t >> 3) ^ (j & 7))) << 4) + (t & 7) * 2);
}

// ---------------- Kernel D: out[b,c,w*T+t] = sum_j A2[c,j] * x[b,w,j,t] ----
// bf16-split mma.sync: 3 passes Ah*xh + Ah*xl + Al*xh, fp32 accum.
// Block: 256 thr / 8 warps; warp (wid&3) owns c0=(wid&3)*16, (wid>>2) owns t-half.
__global__ __launch_bounds__(256, 2) void k_prop_mma(const float* __restrict__ x,
                                                     float* __restrict__ out) {
    __shared__ __nv_bfloat16 xt[2][64 * 128];   // [0]=hi, [1]=lo (16KB each)
    int tid = threadIdx.x;
    int wid = tid >> 5, lane = tid & 31;
    int bw  = blockIdx.y;               // 0..1023
    int tch = blockIdx.x;               // 0..7 (128-wide t chunks)
    int b = bw >> 4, wwin = bw & 15;

    uint32_t sb_hi = smem_u32(&xt[0][0]);
    uint32_t sb_lo = smem_u32(&xt[1][0]);

    // ---- convert x tile -> bf16 hi/lo into swizzled smem ----
#pragma unroll
    for (int r = 0; r < 8; ++r) {
        int lin = tid + r * 256;          // 0..2047 float4 slots (64 j x 32)
        int j = lin >> 5, q = lin & 31;   // t = 4q
        float4 v = reinterpret_cast<const float4*>(x)[
            (((size_t)bw * CC + j) * TT + (size_t)tch * 128) / 4 + q];
        __nv_bfloat16 h0 = __float2bfloat16(v.x), h1 = __float2bfloat16(v.y);
        __nv_bfloat16 h2 = __float2bfloat16(v.z), h3 = __float2bfloat16(v.w);
        __nv_bfloat16 l0 = __float2bfloat16(v.x - __bfloat162float(h0));
        __nv_bfloat16 l1 = __float2bfloat16(v.y - __bfloat162float(h1));
        __nv_bfloat16 l2 = __float2bfloat16(v.z - __bfloat162float(h2));
        __nv_bfloat16 l3 = __float2bfloat16(v.w - __bfloat162float(h3));
        uint32_t off = xt_off(j, 4 * q);   // 8B aligned (t mult of 4)
        *reinterpret_cast<uint2*>((char*)xt + off) =
            make_uint2(pack2h(h0, h1), pack2h(h2, h3));
        *reinterpret_cast<uint2*>((char*)xt + 16384 + off) =
            make_uint2(pack2h(l0, l1), pack2h(l2, l3));
    }

    // ---- A fragments (load once; L1-resident after first block) ----
    int c0 = (wid & 3) * 16;
    int thalf = wid >> 2;
    int r = lane >> 2, cq = lane & 3, kk = 2 * cq;
    uint32_t Ah[4][4], Al[4][4];
#pragma unroll
    for (int ks = 0; ks < 4; ++ks) {
        int k0 = ks * 16;
        const __nv_bfloat16* ph = g_A2h;
        const __nv_bfloat16* pl = g_A2l;
        Ah[ks][0] = *reinterpret_cast<const uint32_t*>(&ph[(c0 + r) * 64 + k0 + kk]);
        Ah[ks][1] = *reinterpret_cast<const uint32_t*>(&ph[(c0 + r + 8) * 64 + k0 + kk]);
        Ah[ks][2] = *reinterpret_cast<const uint32_t*>(&ph[(c0 + r) * 64 + k0 + kk + 8]);
        Ah[ks][3] = *reinterpret_cast<const uint32_t*>(&ph[(c0 + r + 8) * 64 + k0 + kk + 8]);
        Al[ks][0] = *reinterpret_cast<const uint32_t*>(&pl[(c0 + r) * 64 + k0 + kk]);
        Al[ks][1] = *reinterpret_cast<const uint32_t*>(&pl[(c0 + r + 8) * 64 + k0 + kk]);
        Al[ks][2] = *reinterpret_cast<const uint32_t*>(&pl[(c0 + r) * 64 + k0 + kk + 8]);
        Al[ks][3] = *reinterpret_cast<const uint32_t*>(&pl[(c0 + r + 8) * 64 + k0 + kk + 8]);
    }

    __syncthreads();

    // ---- mainloop: 4 k-steps x 8 n-tiles x 3 passes ----
    float acc[8][4];
#pragma unroll
    for (int n = 0; n < 8; ++n)
#pragma unroll
        for (int i = 0; i < 4; ++i) acc[n][i] = 0.f;

    // ldmatrix lane roles: m = lane>>3 (matrix), i = lane&7 (row within matrix)
    int lm = lane >> 3, li = lane & 7;

#pragma unroll
    for (int ks = 0; ks < 4; ++ks) {
        int kbase = ks * 16 + ((lm & 1) ? 8 : 0) + li;   // j row this lane points at
        uint32_t Bh[4][4], Bl_[4][4];
#pragma unroll
        for (int p = 0; p < 4; ++p) {     // pair p covers ntiles 2p, 2p+1
            int nb = thalf * 64 + p * 16 + ((lm & 2) ? 8 : 0);
            uint32_t a = sb_hi + xt_off(kbase, nb);
            ldsm_x4_t(Bh[p][0], Bh[p][1], Bh[p][2], Bh[p][3], a);
        }
        // pass 1+2: Ah*Bh and Al*Bh
#pragma unroll
        for (int p = 0; p < 4; ++p) {
            int n0 = 2 * p, n1 = 2 * p + 1;
            mma_bf16(acc[n0][0], acc[n0][1], acc[n0][2], acc[n0][3],
                     Ah[ks][0], Ah[ks][1], Ah[ks][2], Ah[ks][3], Bh[p][0], Bh[p][1]);
            mma_bf16(acc[n1][0], acc[n1][1], acc[n1][2], acc[n1][3],
                     Ah[ks][0], Ah[ks][1], Ah[ks][2], Ah[ks][3], Bh[p][2], Bh[p][3]);
            mma_bf16(acc[n0][0], acc[n0][1], acc[n0][2], acc[n0][3],
                     Al[ks][0], Al[ks][1], Al[ks][2], Al[ks][3], Bh[p][0], Bh[p][1]);
            mma_bf16(acc[n1][0], acc[n1][1], acc[n1][2], acc[n1][3],
                     Al[ks][0], Al[ks][1], Al[ks][2], Al[ks][3], Bh[p][2], Bh[p][3]);
        }
        // pass 3: Ah*Bl
#pragma unroll
        for (int p = 0; p < 4; ++p) {
            int nb = thalf * 64 + p * 16 + ((lm & 2) ? 8 : 0);
            uint32_t a = sb_lo + xt_off(kbase, nb);
            ldsm_x4_t(Bl_[p][0], Bl_[p][1], Bl_[p][2], Bl_[p][3], a);
        }
#pragma unroll
        for (int p = 0; p < 4; ++p) {
            int n0 = 2 * p, n1 = 2 * p + 1;
            mma_bf16(acc[n0][0], acc[n0][1], acc[n0][2], acc[n0][3],
                     Ah[ks][0], Ah[ks][1], Ah[ks][2], Ah[ks][3], Bl_[p][0], Bl_[p][1]);
            mma_bf16(acc[n1][0], acc[n1][1], acc[n1][2], acc[n1][3],
                     Ah[ks][0], Ah[ks][1], Ah[ks][2], Ah[ks][3], Bl_[p][2], Bl_[p][3]);
        }
    }

    // ---- epilogue: direct float2 stores (sector-complete) ----
    size_t base = (size_t)b * CC * WT + (size_t)wwin * TT + (size_t)tch * 128
                + thalf * 64;
#pragma unroll
    for (int n = 0; n < 8; ++n) {
        int t = n * 8 + 2 * cq;
        *reinterpret_cast<float2*>(out + base + (size_t)(c0 + r) * WT + t) =
            make_float2(acc[n][0], acc[n][1]);
        *reinterpret_cast<float2*>(out + base + (size_t)(c0 + r + 8) * WT + t) =
            make_float2(acc[n][2], acc[n][3]);
    }
}

// ---------------- launch ----------------
extern "C" void kernel_launch(void* const* d_in, const int* in_sizes, int n_in,
                              void* d_out, int out_size) {
    const float* x     = (const float*)d_in[0];
    const float* Wp    = (const float*)d_in[1];
    const float* w1    = (const float*)d_in[2];
    const float* b1    = (const float*)d_in[3];
    const float* w2    = (const float*)d_in[4];
    const float* b2    = (const float*)d_in[5];
    const float* beta  = (const float*)d_in[6];
    const float* gamma = (const float*)d_in[7];
    const float* temp  = (const float*)d_in[8];
    float* out = (float*)d_out;
    float* outA = ((size_t)out_size >= XR_SIZE + CC * CC) ? out + XR_SIZE : nullptr;

    k_stats<<<(BW * CC) / 8, 256>>>(x);
    k_Z<<<dim3(CC, 4), 256>>>(Wp);
    k_graph<<<1, 256>>>(w1, b1, w2, b2, beta, gamma, temp, outA);
    dim3 g(8, BW);
    k_prop_mma<<<g, 256>>>(x, out);
}

// round 10
// speedup vs baseline: 1.4103x; 1.0458x over previous
#include <cuda_runtime.h>
#include <cuda_bf16.h>
#include <cstdint>
#include <cstddef>

#define BB 64
#define WW 16
#define CC 64
#define TT 1024
#define DE 64
#define BW (BB*WW)           // 1024
#define WT (WW*TT)           // 16384
#define XR_SIZE ((size_t)BB*CC*WT)  // 67108864

__device__ float g_stat[BW*CC];
__device__ float g_Zpart[4][CC*DE];
// A2 pre-arranged as mma fragments: [mt(4)][ks(4)][lane(32)][reg(4)] uint32(bf16x2)
__device__ uint32_t g_A2fh[4*4*32*4];
__device__ uint32_t g_A2fl[4*4*32*4];

// ---------------- Kernel A: per-(b,w,c) robust stats ----------------
__global__ void k_stats(const float* __restrict__ x) {
    int row  = blockIdx.x * 8 + (threadIdx.x >> 5);   // 0..65535
    int lane = threadIdx.x & 31;
    const float4* xv = reinterpret_cast<const float4*>(x + (size_t)row * TT);
    float s1 = 0.f, s2 = 0.f;
#pragma unroll
    for (int i = 0; i < 8; ++i) {
        float4 v = xv[lane + i * 32];
        s1 += v.x + v.y + v.z + v.w;
        s2 += v.x*v.x + v.y*v.y + v.z*v.z + v.w*v.w;
    }
#pragma unroll
    for (int off = 16; off; off >>= 1) {
        s1 += __shfl_down_sync(0xffffffffu, s1, off);
        s2 += __shfl_down_sync(0xffffffffu, s2, off);
    }
    if (lane == 0) g_stat[row] = (s1 + s2) * (0.5f / TT);
}

// ---------------- Kernel B: partial Z over i-quarters ----------------
__global__ void k_Z(const float* __restrict__ Wp) {
    __shared__ float sstat[256];
    __shared__ float part[4][DE];
    int c = blockIdx.x;
    int pr = blockIdx.y;
    int base = pr * 256;
    sstat[threadIdx.x] = g_stat[(base + threadIdx.x) * CC + c];
    __syncthreads();
    int d = threadIdx.x & 63;
    int p = threadIdx.x >> 6;
    float w = Wp[d];
    float acc = 0.f;
    int i0 = p * 64;
    for (int i = i0; i < i0 + 64; ++i) acc += tanhf(sstat[i] * w);
    part[p][d] = acc;
    __syncthreads();
    if (threadIdx.x < DE) {
        g_Zpart[pr][c * DE + threadIdx.x] =
            part[0][threadIdx.x] + part[1][threadIdx.x] +
            part[2][threadIdx.x] + part[3][threadIdx.x];
    }
}

// ---------------- threefry2x32 (JAX partitionable) + gumbel ----------------
__device__ __forceinline__ uint32_t rotl32(uint32_t v, int d) {
    return (v << d) | (v >> (32 - d));
}

__device__ __forceinline__ void threefry_0_42(uint32_t x0, uint32_t x1,
                                              uint32_t& o0, uint32_t& o1) {
    const uint32_t k0 = 0u, k1 = 42u, k2 = 0u ^ 42u ^ 0x1BD11BDAu;
    x0 += k0; x1 += k1;
#define TF_R(r) { x0 += x1; x1 = rotl32(x1, r); x1 ^= x0; }
    TF_R(13) TF_R(15) TF_R(26) TF_R(6)   x0 += k1; x1 += k2 + 1u;
    TF_R(17) TF_R(29) TF_R(16) TF_R(24)  x0 += k2; x1 += k0 + 2u;
    TF_R(13) TF_R(15) TF_R(26) TF_R(6)   x0 += k0; x1 += k1 + 3u;
    TF_R(17) TF_R(29) TF_R(16) TF_R(24)  x0 += k1; x1 += k2 + 4u;
    TF_R(13) TF_R(15) TF_R(26) TF_R(6)   x0 += k2; x1 += k0 + 5u;
#undef TF_R
    o0 = x0; o1 = x1;
}

__device__ __forceinline__ float gumbel_at(int n) {
    uint32_t b0, b1;
    threefry_0_42(0u, (uint32_t)n, b0, b1);
    uint32_t bits = b0 ^ b1;
    float u = __uint_as_float((bits >> 9) | 0x3f800000u) - 1.0f;
    const float tiny = 1.17549435e-38f;
    float v = fmaxf(u, tiny);
    return -logf(-logf(v));
}

// ---------------- Kernel C: graph construction (single block, 256 thr) ----------------
__global__ void k_graph(const float* __restrict__ w1, const float* __restrict__ b1,
                        const float* __restrict__ w2, const float* __restrict__ b2,
                        const float* __restrict__ beta_p, const float* __restrict__ gamma_p,
                        const float* __restrict__ temp_p, float* __restrict__ outA) {
    __shared__ float sZ[CC * DE];
    __shared__ float sA[CC * CC];
    __shared__ float sB[CC * CC];
    __shared__ float sy[CC * 68];          // padded rows: conflict-free scan
    int tid = threadIdx.x;

    for (int i = tid; i < CC * DE; i += 256)
        sZ[i] = (g_Zpart[0][i] + g_Zpart[1][i] + g_Zpart[2][i] + g_Zpart[3][i])
                * (1.0f / BW);
    __syncthreads();

    if (tid < CC) {
        float s = 0.f;
        for (int d = 0; d < DE; ++d) { float z = sZ[tid * DE + d]; s += z * z; }
        sB[tid] = s;  // sq
    }
    __syncthreads();

    float d2r[16];
    int e0 = tid * 16;
    int irow = tid >> 2, jq = (tid & 3) * 16;
#pragma unroll
    for (int k = 0; k < 16; ++k) {
        int e = e0 + k; int i = e >> 6, j = e & 63;
        float dot = 0.f;
        for (int d = 0; d < DE; ++d) dot += sZ[i * DE + d] * sZ[j * DE + d];
        float v = sB[i] + sB[j] - 2.0f * dot;
        d2r[k] = fmaxf(v, 0.f) * 0.5f;
        sA[e] = (i == j) ? 1.f : 0.f;
    }
    __syncthreads();

    float lw1[16], lb1[16], lw2[16];
#pragma unroll
    for (int h = 0; h < 16; ++h) { lw1[h] = w1[h]; lb1[h] = b1[h]; lw2[h] = w2[h]; }
    float lb2 = b2[0];
    float beta = beta_p[0], gamma = gamma_p[0];
    const float inv_sqrt2 = 0.70710678118654752440f;

    for (int s = 0; s < 2; ++s) {
#pragma unroll
        for (int k = 0; k < 16; ++k) {
            int e = e0 + k;
            float a = sA[e] - 0.2f * d2r[k];
            float acc = lb2;
#pragma unroll
            for (int h = 0; h < 16; ++h) {
                float z = a * lw1[h] + lb1[h];
                float gel = 0.5f * z * (1.0f + erff(z * inv_sqrt2));
                acc += gel * lw2[h];
            }
            float delta = fmaxf(acc, 0.f) + log1pf(expf(-fabsf(acc)));
            sB[e] = a + beta * (delta * gamma);
        }
        __syncthreads();
#pragma unroll
        for (int k = 0; k < 16; ++k) {
            int e = e0 + k; int i = e >> 6, j = e & 63;
            float v = 0.5f * (sB[e] + sB[j * CC + i]);
            sA[e] = fmaxf(v, 0.f) + ((i == j) ? 1.f : 0.f);
        }
        __syncthreads();
    }

    // ---- Gumbel top-k via parallel rank counting (all 256 threads) ----
    // rank_j = #{k: y_k > y_j, or y_k == y_j and k < j}; keep rank < 16.
    // Exactly matches lax.top_k's stable (lowest-index-first) selection.
    {
        float invT = 1.0f / fmaxf(temp_p[0], 1e-6f);
        float yl[16];
#pragma unroll
        for (int jj = 0; jj < 16; ++jj) {
            int j = jq + jj;
            float y = (sA[irow * 64 + j] + gumbel_at(irow * 64 + j)) * invT;
            yl[jj] = y;
            sy[irow * 68 + j] = y;
        }
        __syncthreads();
        int rank[16];
#pragma unroll
        for (int jj = 0; jj < 16; ++jj) rank[jj] = 0;
        for (int k = 0; k < 64; ++k) {
            float yk = sy[irow * 68 + k];
#pragma unroll
            for (int jj = 0; jj < 16; ++jj) {
                int j = jq + jj;
                rank[jj] += (yk > yl[jj]) || (yk == yl[jj] && k < j);
            }
        }
#pragma unroll
        for (int jj = 0; jj < 16; ++jj) {
            int j = jq + jj;
            sB[irow * 64 + j] = (rank[jj] < 16) ? sA[irow * 64 + j] : 0.f;
        }
    }
    __syncthreads();

#pragma unroll
    for (int k = 0; k < 16; ++k) {
        int e = e0 + k; int i = e >> 6, j = e & 63;
        float v = 0.5f * (sB[e] + sB[j * CC + i]);
        sA[e] = fmaxf(v, 0.f) + ((i == j) ? 1.f : 0.f);
    }
    __syncthreads();

    if (tid < CC) {
        float s = 0.f;
        for (int j = 0; j < CC; ++j) s += sA[tid * CC + j];
        sy[tid] = 1.0f / sqrtf(fmaxf(s, 1e-6f));   // d^{-1/2}
    }
    __syncthreads();

#pragma unroll
    for (int k = 0; k < 16; ++k) {
        int e = e0 + k; int i = e >> 6, j = e & 63;
        float v = (sy[i] * sA[e]) * sy[j];
        sB[e] = v + ((i == j) ? 1.f : 0.f);        // final A
    }
    __syncthreads();

    // A2 = A @ A into sA (scratch), emit A
#pragma unroll
    for (int k = 0; k < 16; ++k) {
        int e = e0 + k;
        if (outA) outA[e] = sB[e];
        int i = e >> 6, j = e & 63;
        float acc = 0.f;
        for (int q = 0; q < CC; ++q) acc += sB[i * CC + q] * sB[q * CC + j];
        sA[e] = acc;
    }
    __syncthreads();

    // Pack A2 into bf16 hi/lo mma fragments:
    // word w: reg = w&3, lane = (w>>2)&31, ks = (w>>7)&3, mt = w>>9
    // c = mt*16 + (lane>>2) + (reg&1)*8 ; k = ks*16 + 2*(lane&3) + (reg>>1)*8
    for (int w = tid; w < 4 * 4 * 32 * 4; w += 256) {
        int reg = w & 3, lane = (w >> 2) & 31, ks = (w >> 7) & 3, mt = w >> 9;
        int c = mt * 16 + (lane >> 2) + (reg & 1) * 8;
        int k = ks * 16 + 2 * (lane & 3) + ((reg >> 1) & 1) * 8;
        float v0 = sA[c * 64 + k], v1 = sA[c * 64 + k + 1];
        __nv_bfloat16 h0 = __float2bfloat16(v0), h1 = __float2bfloat16(v1);
        __nv_bfloat16 l0 = __float2bfloat16(v0 - __bfloat162float(h0));
        __nv_bfloat16 l1 = __float2bfloat16(v1 - __bfloat162float(h1));
        g_A2fh[w] = (uint32_t)__bfloat16_as_ushort(h0) |
                    ((uint32_t)__bfloat16_as_ushort(h1) << 16);
        g_A2fl[w] = (uint32_t)__bfloat16_as_ushort(l0) |
                    ((uint32_t)__bfloat16_as_ushort(l1) << 16);
    }
}

// ================== mma.sync bf16 helpers (sm_80+ PTX, compute_103-safe) ====
__device__ __forceinline__ uint32_t smem_u32(const void* p) {
    uint32_t a;
    asm("{ .reg .u64 t; cvta.to.shared.u64 t, %1; cvt.u32.u64 %0, t; }"
        : "=r"(a) : "l"(p));
    return a;
}

__device__ __forceinline__ void ldsm_x4_t(uint32_t& d0, uint32_t& d1,
                                          uint32_t& d2, uint32_t& d3,
                                          uint32_t addr) {
    asm volatile(
        "ldmatrix.sync.aligned.m8n8.x4.trans.shared.b16 {%0,%1,%2,%3}, [%4];"
        : "=r"(d0), "=r"(d1), "=r"(d2), "=r"(d3) : "r"(addr));
}

__device__ __forceinline__ void mma_bf16(float& d0, float& d1, float& d2, float& d3,
                                         uint32_t a0, uint32_t a1, uint32_t a2, uint32_t a3,
                                         uint32_t b0, uint32_t b1) {
    asm volatile(
        "mma.sync.aligned.m16n8k16.row.col.f32.bf16.bf16.f32 "
        "{%0,%1,%2,%3}, {%4,%5,%6,%7}, {%8,%9}, {%0,%1,%2,%3};"
        : "+f"(d0), "+f"(d1), "+f"(d2), "+f"(d3)
        : "r"(a0), "r"(a1), "r"(a2), "r"(a3), "r"(b0), "r"(b1));
}

__device__ __forceinline__ uint32_t pack2h(__nv_bfloat16 a, __nv_bfloat16 b) {
    return (uint32_t)__bfloat16_as_ushort(a) |
           ((uint32_t)__bfloat16_as_ushort(b) << 16);
}

// xt tile: [j=0..63][t=0..127] bf16, row = 256B, 16B-chunk XOR swizzle
__device__ __forceinline__ uint32_t xt_off(int j, int t) {
    return (uint32_t)(j * 256 + ((((t >> 3) ^ (j & 7))) << 4) + (t & 7) * 2);
}

// ---------------- Kernel D: out[b,c,w*T+t] = sum_j A2[c,j] * x[b,w,j,t] ----
// bf16-split mma.sync, warp tile 32c x 32t (2 c-groups x 4 t-groups):
// halves B ldmatrix duplication vs 16c x 64t; A via coalesced fragment LDG.128.
__global__ __launch_bounds__(256, 2) void k_prop_mma(const float* __restrict__ x,
                                                     float* __restrict__ out) {
    __shared__ __nv_bfloat16 xt[2][64 * 128];   // [0]=hi, [1]=lo (16KB each)
    int tid = threadIdx.x;
    int wid = tid >> 5, lane = tid & 31;
    int bw  = blockIdx.y;               // 0..1023
    int tch = blockIdx.x;               // 0..7 (128-wide t chunks)
    int b = bw >> 4, wwin = bw & 15;

    uint32_t sb_hi = smem_u32(&xt[0][0]);
    uint32_t sb_lo = smem_u32(&xt[1][0]);

    // ---- convert x tile -> bf16 hi/lo into swizzled smem ----
#pragma unroll
    for (int r = 0; r < 8; ++r) {
        int lin = tid + r * 256;          // 0..2047 float4 slots (64 j x 32)
        int j = lin >> 5, q = lin & 31;   // t = 4q
        float4 v = reinterpret_cast<const float4*>(x)[
            (((size_t)bw * CC + j) * TT + (size_t)tch * 128) / 4 + q];
        __nv_bfloat16 h0 = __float2bfloat16(v.x), h1 = __float2bfloat16(v.y);
        __nv_bfloat16 h2 = __float2bfloat16(v.z), h3 = __float2bfloat16(v.w);
        __nv_bfloat16 l0 = __float2bfloat16(v.x - __bfloat162float(h0));
        __nv_bfloat16 l1 = __float2bfloat16(v.y - __bfloat162float(h1));
        __nv_bfloat16 l2 = __float2bfloat16(v.z - __bfloat162float(h2));
        __nv_bfloat16 l3 = __float2bfloat16(v.w - __bfloat162float(h3));
        uint32_t off = xt_off(j, 4 * q);
        *reinterpret_cast<uint2*>((char*)xt + off) =
            make_uint2(pack2h(h0, h1), pack2h(h2, h3));
        *reinterpret_cast<uint2*>((char*)xt + 16384 + off) =
            make_uint2(pack2h(l0, l1), pack2h(l2, l3));
    }
    __syncthreads();

    int cg = wid & 1;                 // c half: c0 = cg*32 (2 m16-tiles)
    int tg = wid >> 1;                // t quarter: t0 = tg*32 (4 n8-tiles)
    int c0 = cg * 32, t0 = tg * 32;
    int r = lane >> 2, cq = lane & 3;
    int lm = lane >> 3, li = lane & 7;

    float acc[2][4][4];
#pragma unroll
    for (int m = 0; m < 2; ++m)
#pragma unroll
        for (int n = 0; n < 4; ++n)
#pragma unroll
            for (int i = 0; i < 4; ++i) acc[m][n][i] = 0.f;

    const uint4* fh = reinterpret_cast<const uint4*>(g_A2fh);
    const uint4* fl = reinterpret_cast<const uint4*>(g_A2fl);

#pragma unroll
    for (int ks = 0; ks < 4; ++ks) {
        // A fragments: coalesced LDG.128 of pre-arranged frags
        uint4 ah0 = fh[((cg * 2 + 0) * 4 + ks) * 32 + lane];
        uint4 ah1 = fh[((cg * 2 + 1) * 4 + ks) * 32 + lane];
        uint4 al0 = fl[((cg * 2 + 0) * 4 + ks) * 32 + lane];
        uint4 al1 = fl[((cg * 2 + 1) * 4 + ks) * 32 + lane];

        int kbase = ks * 16 + ((lm & 1) ? 8 : 0) + li;
        uint32_t Bf[2][4];
        // hi B: two x4 covering t0..t0+31
#pragma unroll
        for (int p = 0; p < 2; ++p) {
            int nb = t0 + p * 16 + ((lm & 2) ? 8 : 0);
            ldsm_x4_t(Bf[p][0], Bf[p][1], Bf[p][2], Bf[p][3],
                      sb_hi + xt_off(kbase, nb));
        }
#pragma unroll
        for (int p = 0; p < 2; ++p) {
            int n0 = 2 * p, n1 = 2 * p + 1;
            mma_bf16(acc[0][n0][0], acc[0][n0][1], acc[0][n0][2], acc[0][n0][3],
                     ah0.x, ah0.y, ah0.z, ah0.w, Bf[p][0], Bf[p][1]);
            mma_bf16(acc[0][n1][0], acc[0][n1][1], acc[0][n1][2], acc[0][n1][3],
                     ah0.x, ah0.y, ah0.z, ah0.w, Bf[p][2], Bf[p][3]);
            mma_bf16(acc[1][n0][0], acc[1][n0][1], acc[1][n0][2], acc[1][n0][3],
                     ah1.x, ah1.y, ah1.z, ah1.w, Bf[p][0], Bf[p][1]);
            mma_bf16(acc[1][n1][0], acc[1][n1][1], acc[1][n1][2], acc[1][n1][3],
                     ah1.x, ah1.y, ah1.z, ah1.w, Bf[p][2], Bf[p][3]);
            mma_bf16(acc[0][n0][0], acc[0][n0][1], acc[0][n0][2], acc[0][n0][3],
                     al0.x, al0.y, al0.z, al0.w, Bf[p][0], Bf[p][1]);
            mma_bf16(acc[0][n1][0], acc[0][n1][1], acc[0][n1][2], acc[0][n1][3],
                     al0.x, al0.y, al0.z, al0.w, Bf[p][2], Bf[p][3]);
            mma_bf16(acc[1][n0][0], acc[1][n0][1], acc[1][n0][2], acc[1][n0][3],
                     al1.x, al1.y, al1.z, al1.w, Bf[p][0], Bf[p][1]);
            mma_bf16(acc[1][n1][0], acc[1][n1][1], acc[1][n1][2], acc[1][n1][3],
                     al1.x, al1.y, al1.z, al1.w, Bf[p][2], Bf[p][3]);
        }
        // lo B (x_lo) with Ah
#pragma unroll
        for (int p = 0; p < 2; ++p) {
            int nb = t0 + p * 16 + ((lm & 2) ? 8 : 0);
            ldsm_x4_t(Bf[p][0], Bf[p][1], Bf[p][2], Bf[p][3],
                      sb_lo + xt_off(kbase, nb));
        }
#pragma unroll
        for (int p = 0; p < 2; ++p) {
            int n0 = 2 * p, n1 = 2 * p + 1;
            mma_bf16(acc[0][n0][0], acc[0][n0][1], acc[0][n0][2], acc[0][n0][3],
                     ah0.x, ah0.y, ah0.z, ah0.w, Bf[p][0], Bf[p][1]);
            mma_bf16(acc[0][n1][0], acc[0][n1][1], acc[0][n1][2], acc[0][n1][3],
                     ah0.x, ah0.y, ah0.z, ah0.w, Bf[p][2], Bf[p][3]);
            mma_bf16(acc[1][n0][0], acc[1][n0][1], acc[1][n0][2], acc[1][n0][3],
                     ah1.x, ah1.y, ah1.z, ah1.w, Bf[p][0], Bf[p][1]);
            mma_bf16(acc[1][n1][0], acc[1][n1][1], acc[1][n1][2], acc[1][n1][3],
                     ah1.x, ah1.y, ah1.z, ah1.w, Bf[p][2], Bf[p][3]);
        }
    }

    // ---- epilogue: direct float2 stores ----
    size_t base = (size_t)b * CC * WT + (size_t)wwin * TT + (size_t)tch * 128 + t0;
#pragma unroll
    for (int m = 0; m < 2; ++m) {
        int cr = c0 + m * 16 + r;
#pragma unroll
        for (int n = 0; n < 4; ++n) {
            int t = n * 8 + 2 * cq;
            *reinterpret_cast<float2*>(out + base + (size_t)cr * WT + t) =
                make_float2(acc[m][n][0], acc[m][n][1]);
            *reinterpret_cast<float2*>(out + base + (size_t)(cr + 8) * WT + t) =
                make_float2(acc[m][n][2], acc[m][n][3]);
        }
    }
}

// ---------------- launch ----------------
extern "C" void kernel_launch(void* const* d_in, const int* in_sizes, int n_in,
                              void* d_out, int out_size) {
    const float* x     = (const float*)d_in[0];
    const float* Wp    = (const float*)d_in[1];
    const float* w1    = (const float*)d_in[2];
    const float* b1    = (const float*)d_in[3];
    const float* w2    = (const float*)d_in[4];
    const float* b2    = (const float*)d_in[5];
    const float* beta  = (const float*)d_in[6];
    const float* gamma = (const float*)d_in[7];
    const float* temp  = (const float*)d_in[8];
    float* out = (float*)d_out;
    float* outA = ((size_t)out_size >= XR_SIZE + CC * CC) ? out + XR_SIZE : nullptr;

    k_stats<<<(BW * CC) / 8, 256>>>(x);
    k_Z<<<dim3(CC, 4), 256>>>(Wp);
    k_graph<<<1, 256>>>(w1, b1, w2, b2, beta, gamma, temp, outA);
    dim3 g(8, BW);
    k_prop_mma<<<g, 256>>>(x, out);
}

// round 11
// speedup vs baseline: 1.7156x; 1.2165x over previous
#include <cuda_runtime.h>
#include <cuda_bf16.h>
#include <cstdint>
#include <cstddef>

#define BB 64
#define WW 16
#define CC 64
#define TT 1024
#define DE 64
#define BW (BB*WW)           // 1024
#define WT (WW*TT)           // 16384
#define XR_SIZE ((size_t)BB*CC*WT)  // 67108864

__device__ float g_stat[BW*CC];
__device__ float g_Zpart[4][CC*DE];
// A2 pre-arranged as mma fragments: [mt(4)][ks(4)][lane(32)][reg(4)] uint32(bf16x2)
__device__ uint32_t g_A2fh[4*4*32*4];
__device__ uint32_t g_A2fl[4*4*32*4];

// ---------------- Kernel A: per-(b,w,c) robust stats ----------------
__global__ void k_stats(const float* __restrict__ x) {
    int row  = blockIdx.x * 8 + (threadIdx.x >> 5);   // 0..65535
    int lane = threadIdx.x & 31;
    const float4* xv = reinterpret_cast<const float4*>(x + (size_t)row * TT);
    float s1 = 0.f, s2 = 0.f;
#pragma unroll
    for (int i = 0; i < 8; ++i) {
        float4 v = xv[lane + i * 32];
        s1 += v.x + v.y + v.z + v.w;
        s2 += v.x*v.x + v.y*v.y + v.z*v.z + v.w*v.w;
    }
#pragma unroll
    for (int off = 16; off; off >>= 1) {
        s1 += __shfl_down_sync(0xffffffffu, s1, off);
        s2 += __shfl_down_sync(0xffffffffu, s2, off);
    }
    if (lane == 0) g_stat[row] = (s1 + s2) * (0.5f / TT);
}

// ---------------- Kernel B: partial Z over i-quarters ----------------
__global__ void k_Z(const float* __restrict__ Wp) {
    __shared__ float sstat[256];
    __shared__ float part[4][DE];
    int c = blockIdx.x;
    int pr = blockIdx.y;
    int base = pr * 256;
    sstat[threadIdx.x] = g_stat[(base + threadIdx.x) * CC + c];
    __syncthreads();
    int d = threadIdx.x & 63;
    int p = threadIdx.x >> 6;
    float w = Wp[d];
    float acc = 0.f;
    int i0 = p * 64;
    for (int i = i0; i < i0 + 64; ++i) acc += tanhf(sstat[i] * w);
    part[p][d] = acc;
    __syncthreads();
    if (threadIdx.x < DE) {
        g_Zpart[pr][c * DE + threadIdx.x] =
            part[0][threadIdx.x] + part[1][threadIdx.x] +
            part[2][threadIdx.x] + part[3][threadIdx.x];
    }
}

// ---------------- threefry2x32 (JAX partitionable) + gumbel ----------------
__device__ __forceinline__ uint32_t rotl32(uint32_t v, int d) {
    return (v << d) | (v >> (32 - d));
}

__device__ __forceinline__ void threefry_0_42(uint32_t x0, uint32_t x1,
                                              uint32_t& o0, uint32_t& o1) {
    const uint32_t k0 = 0u, k1 = 42u, k2 = 0u ^ 42u ^ 0x1BD11BDAu;
    x0 += k0; x1 += k1;
#define TF_R(r) { x0 += x1; x1 = rotl32(x1, r); x1 ^= x0; }
    TF_R(13) TF_R(15) TF_R(26) TF_R(6)   x0 += k1; x1 += k2 + 1u;
    TF_R(17) TF_R(29) TF_R(16) TF_R(24)  x0 += k2; x1 += k0 + 2u;
    TF_R(13) TF_R(15) TF_R(26) TF_R(6)   x0 += k0; x1 += k1 + 3u;
    TF_R(17) TF_R(29) TF_R(16) TF_R(24)  x0 += k1; x1 += k2 + 4u;
    TF_R(13) TF_R(15) TF_R(26) TF_R(6)   x0 += k2; x1 += k0 + 5u;
#undef TF_R
    o0 = x0; o1 = x1;
}

__device__ __forceinline__ float gumbel_at(int n) {
    uint32_t b0, b1;
    threefry_0_42(0u, (uint32_t)n, b0, b1);
    uint32_t bits = b0 ^ b1;
    float u = __uint_as_float((bits >> 9) | 0x3f800000u) - 1.0f;
    const float tiny = 1.17549435e-38f;
    float v = fmaxf(u, tiny);
    return -logf(-logf(v));
}

// ---------------- Kernel C: graph construction (single block, 512 thr) ----------------
// 512 threads, 8 elements each (was 256x16): doubles warps/SMSP on the single
// resident SM to hide smem/MUFU latency in this serial-chain kernel.
__global__ void k_graph(const float* __restrict__ w1, const float* __restrict__ b1,
                        const float* __restrict__ w2, const float* __restrict__ b2,
                        const float* __restrict__ beta_p, const float* __restrict__ gamma_p,
                        const float* __restrict__ temp_p, float* __restrict__ outA) {
    __shared__ float sZ[CC * DE];
    __shared__ float sA[CC * CC];
    __shared__ float sB[CC * CC];
    __shared__ float sy[CC * 68];          // padded rows: conflict-free scan
    int tid = threadIdx.x;

    for (int i = tid; i < CC * DE; i += 512)
        sZ[i] = (g_Zpart[0][i] + g_Zpart[1][i] + g_Zpart[2][i] + g_Zpart[3][i])
                * (1.0f / BW);
    __syncthreads();

    if (tid < CC) {
        float s = 0.f;
        for (int d = 0; d < DE; ++d) { float z = sZ[tid * DE + d]; s += z * z; }
        sB[tid] = s;  // sq
    }
    __syncthreads();

    float d2r[8];
    int e0 = tid * 8;
    int irow = tid >> 3, jq = (tid & 7) * 8;
#pragma unroll
    for (int k = 0; k < 8; ++k) {
        int e = e0 + k; int i = e >> 6, j = e & 63;
        float dot = 0.f;
        for (int d = 0; d < DE; ++d) dot += sZ[i * DE + d] * sZ[j * DE + d];
        float v = sB[i] + sB[j] - 2.0f * dot;
        d2r[k] = fmaxf(v, 0.f) * 0.5f;
        sA[e] = (i == j) ? 1.f : 0.f;
    }
    __syncthreads();

    float lw1[16], lb1[16], lw2[16];
#pragma unroll
    for (int h = 0; h < 16; ++h) { lw1[h] = w1[h]; lb1[h] = b1[h]; lw2[h] = w2[h]; }
    float lb2 = b2[0];
    float beta = beta_p[0], gamma = gamma_p[0];
    const float inv_sqrt2 = 0.70710678118654752440f;

    for (int s = 0; s < 2; ++s) {
#pragma unroll
        for (int k = 0; k < 8; ++k) {
            int e = e0 + k;
            float a = sA[e] - 0.2f * d2r[k];
            float acc = lb2;
#pragma unroll
            for (int h = 0; h < 16; ++h) {
                float z = a * lw1[h] + lb1[h];
                float gel = 0.5f * z * (1.0f + erff(z * inv_sqrt2));
                acc += gel * lw2[h];
            }
            float delta = fmaxf(acc, 0.f) + log1pf(expf(-fabsf(acc)));
            sB[e] = a + beta * (delta * gamma);
        }
        __syncthreads();
#pragma unroll
        for (int k = 0; k < 8; ++k) {
            int e = e0 + k; int i = e >> 6, j = e & 63;
            float v = 0.5f * (sB[e] + sB[j * CC + i]);
            sA[e] = fmaxf(v, 0.f) + ((i == j) ? 1.f : 0.f);
        }
        __syncthreads();
    }

    // ---- Gumbel top-k via parallel rank counting (all 512 threads) ----
    // rank_j = #{k: y_k > y_j, or y_k == y_j and k < j}; keep rank < 16.
    {
        float invT = 1.0f / fmaxf(temp_p[0], 1e-6f);
        float yl[8];
#pragma unroll
        for (int jj = 0; jj < 8; ++jj) {
            int j = jq + jj;
            float y = (sA[irow * 64 + j] + gumbel_at(irow * 64 + j)) * invT;
            yl[jj] = y;
            sy[irow * 68 + j] = y;
        }
        __syncthreads();
        int rank[8];
#pragma unroll
        for (int jj = 0; jj < 8; ++jj) rank[jj] = 0;
        for (int k = 0; k < 64; ++k) {
            float yk = sy[irow * 68 + k];
#pragma unroll
            for (int jj = 0; jj < 8; ++jj) {
                int j = jq + jj;
                rank[jj] += (yk > yl[jj]) || (yk == yl[jj] && k < j);
            }
        }
#pragma unroll
        for (int jj = 0; jj < 8; ++jj) {
            int j = jq + jj;
            sB[irow * 64 + j] = (rank[jj] < 16) ? sA[irow * 64 + j] : 0.f;
        }
    }
    __syncthreads();

#pragma unroll
    for (int k = 0; k < 8; ++k) {
        int e = e0 + k; int i = e >> 6, j = e & 63;
        float v = 0.5f * (sB[e] + sB[j * CC + i]);
        sA[e] = fmaxf(v, 0.f) + ((i == j) ? 1.f : 0.f);
    }
    __syncthreads();

    if (tid < CC) {
        float s = 0.f;
        for (int j = 0; j < CC; ++j) s += sA[tid * CC + j];
        sy[tid] = 1.0f / sqrtf(fmaxf(s, 1e-6f));   // d^{-1/2}
    }
    __syncthreads();

#pragma unroll
    for (int k = 0; k < 8; ++k) {
        int e = e0 + k; int i = e >> 6, j = e & 63;
        float v = (sy[i] * sA[e]) * sy[j];
        sB[e] = v + ((i == j) ? 1.f : 0.f);        // final A
    }
    __syncthreads();

    // A2 = A @ A into sA (scratch), emit A
#pragma unroll
    for (int k = 0; k < 8; ++k) {
        int e = e0 + k;
        if (outA) outA[e] = sB[e];
        int i = e >> 6, j = e & 63;
        float acc = 0.f;
        for (int q = 0; q < CC; ++q) acc += sB[i * CC + q] * sB[q * CC + j];
        sA[e] = acc;
    }
    __syncthreads();

    // Pack A2 into bf16 hi/lo mma fragments:
    // word w: reg = w&3, lane = (w>>2)&31, ks = (w>>7)&3, mt = w>>9
    // c = mt*16 + (lane>>2) + (reg&1)*8 ; k = ks*16 + 2*(lane&3) + (reg>>1)*8
    for (int w = tid; w < 4 * 4 * 32 * 4; w += 512) {
        int reg = w & 3, lane = (w >> 2) & 31, ks = (w >> 7) & 3, mt = w >> 9;
        int c = mt * 16 + (lane >> 2) + (reg & 1) * 8;
        int k = ks * 16 + 2 * (lane & 3) + ((reg >> 1) & 1) * 8;
        float v0 = sA[c * 64 + k], v1 = sA[c * 64 + k + 1];
        __nv_bfloat16 h0 = __float2bfloat16(v0), h1 = __float2bfloat16(v1);
        __nv_bfloat16 l0 = __float2bfloat16(v0 - __bfloat162float(h0));
        __nv_bfloat16 l1 = __float2bfloat16(v1 - __bfloat162float(h1));
        g_A2fh[w] = (uint32_t)__bfloat16_as_ushort(h0) |
                    ((uint32_t)__bfloat16_as_ushort(h1) << 16);
        g_A2fl[w] = (uint32_t)__bfloat16_as_ushort(l0) |
                    ((uint32_t)__bfloat16_as_ushort(l1) << 16);
    }
}

// ================== mma.sync bf16 helpers (sm_80+ PTX, compute_103-safe) ====
__device__ __forceinline__ uint32_t smem_u32(const void* p) {
    uint32_t a;
    asm("{ .reg .u64 t; cvta.to.shared.u64 t, %1; cvt.u32.u64 %0, t; }"
        : "=r"(a) : "l"(p));
    return a;
}

__device__ __forceinline__ void ldsm_x4_t(uint32_t& d0, uint32_t& d1,
                                          uint32_t& d2, uint32_t& d3,
                                          uint32_t addr) {
    asm volatile(
        "ldmatrix.sync.aligned.m8n8.x4.trans.shared.b16 {%0,%1,%2,%3}, [%4];"
        : "=r"(d0), "=r"(d1), "=r"(d2), "=r"(d3) : "r"(addr));
}

__device__ __forceinline__ void mma_bf16(float& d0, float& d1, float& d2, float& d3,
                                         uint32_t a0, uint32_t a1, uint32_t a2, uint32_t a3,
                                         uint32_t b0, uint32_t b1) {
    asm volatile(
        "mma.sync.aligned.m16n8k16.row.col.f32.bf16.bf16.f32 "
        "{%0,%1,%2,%3}, {%4,%5,%6,%7}, {%8,%9}, {%0,%1,%2,%3};"
        : "+f"(d0), "+f"(d1), "+f"(d2), "+f"(d3)
        : "r"(a0), "r"(a1), "r"(a2), "r"(a3), "r"(b0), "r"(b1));
}

__device__ __forceinline__ uint32_t pack2h(__nv_bfloat16 a, __nv_bfloat16 b) {
    return (uint32_t)__bfloat16_as_ushort(a) |
           ((uint32_t)__bfloat16_as_ushort(b) << 16);
}

// xt tile: [j=0..63][t=0..127] bf16, row = 256B, 16B-chunk XOR swizzle
__device__ __forceinline__ uint32_t xt_off(int j, int t) {
    return (uint32_t)(j * 256 + ((((t >> 3) ^ (j & 7))) << 4) + (t & 7) * 2);
}

// ---------------- Kernel D: out[b,c,w*T+t] = sum_j A2[c,j] * x[b,w,j,t] ----
// bf16-split mma.sync, warp tile 32c x 32t (2 c-groups x 4 t-groups).
__global__ __launch_bounds__(256, 2) void k_prop_mma(const float* __restrict__ x,
                                                     float* __restrict__ out) {
    __shared__ __nv_bfloat16 xt[2][64 * 128];   // [0]=hi, [1]=lo (16KB each)
    int tid = threadIdx.x;
    int wid = tid >> 5, lane = tid & 31;
    int bw  = blockIdx.y;               // 0..1023
    int tch = blockIdx.x;               // 0..7 (128-wide t chunks)
    int b = bw >> 4, wwin = bw & 15;

    uint32_t sb_hi = smem_u32(&xt[0][0]);
    uint32_t sb_lo = smem_u32(&xt[1][0]);

    // ---- convert x tile -> bf16 hi/lo into swizzled smem ----
#pragma unroll
    for (int r = 0; r < 8; ++r) {
        int lin = tid + r * 256;          // 0..2047 float4 slots (64 j x 32)
        int j = lin >> 5, q = lin & 31;   // t = 4q
        float4 v = reinterpret_cast<const float4*>(x)[
            (((size_t)bw * CC + j) * TT + (size_t)tch * 128) / 4 + q];
        __nv_bfloat16 h0 = __float2bfloat16(v.x), h1 = __float2bfloat16(v.y);
        __nv_bfloat16 h2 = __float2bfloat16(v.z), h3 = __float2bfloat16(v.w);
        __nv_bfloat16 l0 = __float2bfloat16(v.x - __bfloat162float(h0));
        __nv_bfloat16 l1 = __float2bfloat16(v.y - __bfloat162float(h1));
        __nv_bfloat16 l2 = __float2bfloat16(v.z - __bfloat162float(h2));
        __nv_bfloat16 l3 = __float2bfloat16(v.w - __bfloat162float(h3));
        uint32_t off = xt_off(j, 4 * q);
        *reinterpret_cast<uint2*>((char*)xt + off) =
            make_uint2(pack2h(h0, h1), pack2h(h2, h3));
        *reinterpret_cast<uint2*>((char*)xt + 16384 + off) =
            make_uint2(pack2h(l0, l1), pack2h(l2, l3));
    }
    __syncthreads();

    int cg = wid & 1;                 // c half: c0 = cg*32 (2 m16-tiles)
    int tg = wid >> 1;                // t quarter: t0 = tg*32 (4 n8-tiles)
    int c0 = cg * 32, t0 = tg * 32;
    int r = lane >> 2, cq = lane & 3;
    int lm = lane >> 3, li = lane & 7;

    float acc[2][4][4];
#pragma unroll
    for (int m = 0; m < 2; ++m)
#pragma unroll
        for (int n = 0; n < 4; ++n)
#pragma unroll
            for (int i = 0; i < 4; ++i) acc[m][n][i] = 0.f;

    const uint4* fh = reinterpret_cast<const uint4*>(g_A2fh);
    const uint4* fl = reinterpret_cast<const uint4*>(g_A2fl);

#pragma unroll
    for (int ks = 0; ks < 4; ++ks) {
        // A fragments: coalesced LDG.128 of pre-arranged frags
        uint4 ah0 = fh[((cg * 2 + 0) * 4 + ks) * 32 + lane];
        uint4 ah1 = fh[((cg * 2 + 1) * 4 + ks) * 32 + lane];
        uint4 al0 = fl[((cg * 2 + 0) * 4 + ks) * 32 + lane];
        uint4 al1 = fl[((cg * 2 + 1) * 4 + ks) * 32 + lane];

        int kbase = ks * 16 + ((lm & 1) ? 8 : 0) + li;
        uint32_t Bf[2][4];
#pragma unroll
        for (int p = 0; p < 2; ++p) {
            int nb = t0 + p * 16 + ((lm & 2) ? 8 : 0);
            ldsm_x4_t(Bf[p][0], Bf[p][1], Bf[p][2], Bf[p][3],
                      sb_hi + xt_off(kbase, nb));
        }
#pragma unroll
        for (int p = 0; p < 2; ++p) {
            int n0 = 2 * p, n1 = 2 * p + 1;
            mma_bf16(acc[0][n0][0], acc[0][n0][1], acc[0][n0][2], acc[0][n0][3],
                     ah0.x, ah0.y, ah0.z, ah0.w, Bf[p][0], Bf[p][1]);
            mma_bf16(acc[0][n1][0], acc[0][n1][1], acc[0][n1][2], acc[0][n1][3],
                     ah0.x, ah0.y, ah0.z, ah0.w, Bf[p][2], Bf[p][3]);
            mma_bf16(acc[1][n0][0], acc[1][n0][1], acc[1][n0][2], acc[1][n0][3],
                     ah1.x, ah1.y, ah1.z, ah1.w, Bf[p][0], Bf[p][1]);
            mma_bf16(acc[1][n1][0], acc[1][n1][1], acc[1][n1][2], acc[1][n1][3],
                     ah1.x, ah1.y, ah1.z, ah1.w, Bf[p][2], Bf[p][3]);
            mma_bf16(acc[0][n0][0], acc[0][n0][1], acc[0][n0][2], acc[0][n0][3],
                     al0.x, al0.y, al0.z, al0.w, Bf[p][0], Bf[p][1]);
            mma_bf16(acc[0][n1][0], acc[0][n1][1], acc[0][n1][2], acc[0][n1][3],
                     al0.x, al0.y, al0.z, al0.w, Bf[p][2], Bf[p][3]);
            mma_bf16(acc[1][n0][0], acc[1][n0][1], acc[1][n0][2], acc[1][n0][3],
                     al1.x, al1.y, al1.z, al1.w, Bf[p][0], Bf[p][1]);
            mma_bf16(acc[1][n1][0], acc[1][n1][1], acc[1][n1][2], acc[1][n1][3],
                     al1.x, al1.y, al1.z, al1.w, Bf[p][2], Bf[p][3]);
        }
        // lo B (x_lo) with Ah
#pragma unroll
        for (int p = 0; p < 2; ++p) {
            int nb = t0 + p * 16 + ((lm & 2) ? 8 : 0);
            ldsm_x4_t(Bf[p][0], Bf[p][1], Bf[p][2], Bf[p][3],
                      sb_lo + xt_off(kbase, nb));
        }
#pragma unroll
        for (int p = 0; p < 2; ++p) {
            int n0 = 2 * p, n1 = 2 * p + 1;
            mma_bf16(acc[0][n0][0], acc[0][n0][1], acc[0][n0][2], acc[0][n0][3],
                     ah0.x, ah0.y, ah0.z, ah0.w, Bf[p][0], Bf[p][1]);
            mma_bf16(acc[0][n1][0], acc[0][n1][1], acc[0][n1][2], acc[0][n1][3],
                     ah0.x, ah0.y, ah0.z, ah0.w, Bf[p][2], Bf[p][3]);
            mma_bf16(acc[1][n0][0], acc[1][n0][1], acc[1][n0][2], acc[1][n0][3],
                     ah1.x, ah1.y, ah1.z, ah1.w, Bf[p][0], Bf[p][1]);
            mma_bf16(acc[1][n1][0], acc[1][n1][1], acc[1][n1][2], acc[1][n1][3],
                     ah1.x, ah1.y, ah1.z, ah1.w, Bf[p][2], Bf[p][3]);
        }
    }

    // ---- epilogue: direct float2 stores ----
    size_t base = (size_t)b * CC * WT + (size_t)wwin * TT + (size_t)tch * 128 + t0;
#pragma unroll
    for (int m = 0; m < 2; ++m) {
        int cr = c0 + m * 16 + r;
#pragma unroll
        for (int n = 0; n < 4; ++n) {
            int t = n * 8 + 2 * cq;
            *reinterpret_cast<float2*>(out + base + (size_t)cr * WT + t) =
                make_float2(acc[m][n][0], acc[m][n][1]);
            *reinterpret_cast<float2*>(out + base + (size_t)(cr + 8) * WT + t) =
                make_float2(acc[m][n][2], acc[m][n][3]);
        }
    }
}

// ---------------- launch ----------------
extern "C" void kernel_launch(void* const* d_in, const int* in_sizes, int n_in,
                              void* d_out, int out_size) {
    const float* x     = (const float*)d_in[0];
    const float* Wp    = (const float*)d_in[1];
    const float* w1    = (const float*)d_in[2];
    const float* b1    = (const float*)d_in[3];
    const float* w2    = (const float*)d_in[4];
    const float* b2    = (const float*)d_in[5];
    const float* beta  = (const float*)d_in[6];
    const float* gamma = (const float*)d_in[7];
    const float* temp  = (const float*)d_in[8];
    float* out = (float*)d_out;
    float* outA = ((size_t)out_size >= XR_SIZE + CC * CC) ? out + XR_SIZE : nullptr;

    k_stats<<<(BW * CC) / 8, 256>>>(x);
    k_Z<<<dim3(CC, 4), 256>>>(Wp);
    k_graph<<<1, 512>>>(w1, b1, w2, b2, beta, gamma, temp, outA);
    dim3 g(8, BW);
    k_prop_mma<<<g, 256>>>(x, out);
}

// round 15
// speedup vs baseline: 1.8331x; 1.0685x over previous
#include <cuda_runtime.h>
#include <cuda_bf16.h>
#include <cstdint>
#include <cstddef>

#define BB 64
#define WW 16
#define CC 64
#define TT 1024
#define DE 64
#define BW (BB*WW)           // 1024
#define WT (WW*TT)           // 16384
#define XR_SIZE ((size_t)BB*CC*WT)  // 67108864

__device__ float g_stat[BW*CC];
__device__ float g_Zpart[4][CC*DE];
// A2 pre-arranged as mma fragments: [mt(4)][ks(4)][lane(32)][reg(4)] uint32(bf16x2)
__device__ uint32_t g_A2fh[4*4*32*4];
__device__ uint32_t g_A2fl[4*4*32*4];

// ---------------- Kernel A: per-(b,w,c) robust stats ----------------
__global__ void k_stats(const float* __restrict__ x) {
    int row  = blockIdx.x * 8 + (threadIdx.x >> 5);   // 0..65535
    int lane = threadIdx.x & 31;
    const float4* xv = reinterpret_cast<const float4*>(x + (size_t)row * TT);
    float s1 = 0.f, s2 = 0.f;
#pragma unroll
    for (int i = 0; i < 8; ++i) {
        float4 v = xv[lane + i * 32];
        s1 += v.x + v.y + v.z + v.w;
        s2 += v.x*v.x + v.y*v.y + v.z*v.z + v.w*v.w;
    }
#pragma unroll
    for (int off = 16; off; off >>= 1) {
        s1 += __shfl_down_sync(0xffffffffu, s1, off);
        s2 += __shfl_down_sync(0xffffffffu, s2, off);
    }
    if (lane == 0) g_stat[row] = (s1 + s2) * (0.5f / TT);
}

// ---------------- Kernel B: partial Z over i-quarters ----------------
__global__ void k_Z(const float* __restrict__ Wp) {
    __shared__ float sstat[256];
    __shared__ float part[4][DE];
    int c = blockIdx.x;
    int pr = blockIdx.y;
    int base = pr * 256;
    sstat[threadIdx.x] = g_stat[(base + threadIdx.x) * CC + c];
    __syncthreads();
    int d = threadIdx.x & 63;
    int p = threadIdx.x >> 6;
    float w = Wp[d];
    float acc = 0.f;
    int i0 = p * 64;
    for (int i = i0; i < i0 + 64; ++i) acc += tanhf(sstat[i] * w);
    part[p][d] = acc;
    __syncthreads();
    if (threadIdx.x < DE) {
        g_Zpart[pr][c * DE + threadIdx.x] =
            part[0][threadIdx.x] + part[1][threadIdx.x] +
            part[2][threadIdx.x] + part[3][threadIdx.x];
    }
}

// ---------------- threefry2x32 (JAX partitionable) + gumbel ----------------
__device__ __forceinline__ uint32_t rotl32(uint32_t v, int d) {
    return (v << d) | (v >> (32 - d));
}

__device__ __forceinline__ void threefry_0_42(uint32_t x0, uint32_t x1,
                                              uint32_t& o0, uint32_t& o1) {
    const uint32_t k0 = 0u, k1 = 42u, k2 = 0u ^ 42u ^ 0x1BD11BDAu;
    x0 += k0; x1 += k1;
#define TF_R(r) { x0 += x1; x1 = rotl32(x1, r); x1 ^= x0; }
    TF_R(13) TF_R(15) TF_R(26) TF_R(6)   x0 += k1; x1 += k2 + 1u;
    TF_R(17) TF_R(29) TF_R(16) TF_R(24)  x0 += k2; x1 += k0 + 2u;
    TF_R(13) TF_R(15) TF_R(26) TF_R(6)   x0 += k0; x1 += k1 + 3u;
    TF_R(17) TF_R(29) TF_R(16) TF_R(24)  x0 += k1; x1 += k2 + 4u;
    TF_R(13) TF_R(15) TF_R(26) TF_R(6)   x0 += k2; x1 += k0 + 5u;
#undef TF_R
    o0 = x0; o1 = x1;
}

__device__ __forceinline__ float gumbel_at(int n) {
    uint32_t b0, b1;
    threefry_0_42(0u, (uint32_t)n, b0, b1);
    uint32_t bits = b0 ^ b1;
    float u = __uint_as_float((bits >> 9) | 0x3f800000u) - 1.0f;
    const float tiny = 1.17549435e-38f;
    float v = fmaxf(u, tiny);
    return -logf(-logf(v));
}

// ---------------- Kernel C: graph construction (single block, 1024 thr) ----------------
// 1024 threads, 4 elements each, __launch_bounds__ caps regs at 64.
// MLP weights live in shared memory (warp-broadcast LDS) to fit the cap.
__global__ __launch_bounds__(1024, 1)
void k_graph(const float* __restrict__ w1, const float* __restrict__ b1,
             const float* __restrict__ w2, const float* __restrict__ b2,
             const float* __restrict__ beta_p, const float* __restrict__ gamma_p,
             const float* __restrict__ temp_p, float* __restrict__ outA) {
    __shared__ float sZ[CC * DE];
    __shared__ float sA[CC * CC];
    __shared__ float sB[CC * CC];
    __shared__ float sy[CC * 68];          // padded rows: conflict-free scan
    __shared__ float sw1[16], sb1[16], sw2[16];
    __shared__ float sconst[4];            // b2, beta, gamma, invT
    int tid = threadIdx.x;

    if (tid < 16) {
        sw1[tid] = w1[tid];
        sb1[tid] = b1[tid];
        sw2[tid] = w2[tid];
    } else if (tid < 20) {
        if (tid == 16) sconst[0] = b2[0];
        if (tid == 17) sconst[1] = beta_p[0];
        if (tid == 18) sconst[2] = gamma_p[0];
        if (tid == 19) sconst[3] = 1.0f / fmaxf(temp_p[0], 1e-6f);
    }

    for (int i = tid; i < CC * DE; i += 1024)
        sZ[i] = (g_Zpart[0][i] + g_Zpart[1][i] + g_Zpart[2][i] + g_Zpart[3][i])
                * (1.0f / BW);
    __syncthreads();

    if (tid < CC) {
        float s = 0.f;
        for (int d = 0; d < DE; ++d) { float z = sZ[tid * DE + d]; s += z * z; }
        sB[tid] = s;  // sq
    }
    __syncthreads();

    float d2r[4];
    int e0 = tid * 4;
    int irow = tid >> 4, jq = (tid & 15) * 4;
#pragma unroll
    for (int k = 0; k < 4; ++k) {
        int e = e0 + k; int i = e >> 6, j = e & 63;
        float dot = 0.f;
        for (int d = 0; d < DE; ++d) dot += sZ[i * DE + d] * sZ[j * DE + d];
        float v = sB[i] + sB[j] - 2.0f * dot;
        d2r[k] = fmaxf(v, 0.f) * 0.5f;
        sA[e] = (i == j) ? 1.f : 0.f;
    }
    __syncthreads();

    const float inv_sqrt2 = 0.70710678118654752440f;

    for (int s = 0; s < 2; ++s) {
        float lb2 = sconst[0], beta = sconst[1], gamma = sconst[2];
#pragma unroll
        for (int k = 0; k < 4; ++k) {
            int e = e0 + k;
            float a = sA[e] - 0.2f * d2r[k];
            float acc = lb2;
#pragma unroll
            for (int h = 0; h < 16; ++h) {
                float z = a * sw1[h] + sb1[h];
                float gel = 0.5f * z * (1.0f + erff(z * inv_sqrt2));
                acc += gel * sw2[h];
            }
            float delta = fmaxf(acc, 0.f) + log1pf(expf(-fabsf(acc)));
            sB[e] = a + beta * (delta * gamma);
        }
        __syncthreads();
#pragma unroll
        for (int k = 0; k < 4; ++k) {
            int e = e0 + k; int i = e >> 6, j = e & 63;
            float v = 0.5f * (sB[e] + sB[j * CC + i]);
            sA[e] = fmaxf(v, 0.f) + ((i == j) ? 1.f : 0.f);
        }
        __syncthreads();
    }

    // ---- Gumbel top-k via parallel rank counting (all 1024 threads) ----
    // rank_j = #{k: y_k > y_j, or y_k == y_j and k < j}; keep rank < 16.
    {
        float invT = sconst[3];
        float yl[4];
#pragma unroll
        for (int jj = 0; jj < 4; ++jj) {
            int j = jq + jj;
            float y = (sA[irow * 64 + j] + gumbel_at(irow * 64 + j)) * invT;
            yl[jj] = y;
            sy[irow * 68 + j] = y;
        }
        __syncthreads();
        int rank[4];
#pragma unroll
        for (int jj = 0; jj < 4; ++jj) rank[jj] = 0;
        for (int k = 0; k < 64; ++k) {
            float yk = sy[irow * 68 + k];
#pragma unroll
            for (int jj = 0; jj < 4; ++jj) {
                int j = jq + jj;
                rank[jj] += (yk > yl[jj]) || (yk == yl[jj] && k < j);
            }
        }
#pragma unroll
        for (int jj = 0; jj < 4; ++jj) {
            int j = jq + jj;
            sB[irow * 64 + j] = (rank[jj] < 16) ? sA[irow * 64 + j] : 0.f;
        }
    }
    __syncthreads();

#pragma unroll
    for (int k = 0; k < 4; ++k) {
        int e = e0 + k; int i = e >> 6, j = e & 63;
        float v = 0.5f * (sB[e] + sB[j * CC + i]);
        sA[e] = fmaxf(v, 0.f) + ((i == j) ? 1.f : 0.f);
    }
    __syncthreads();

    if (tid < CC) {
        float s = 0.f;
        for (int j = 0; j < CC; ++j) s += sA[tid * CC + j];
        sy[tid] = 1.0f / sqrtf(fmaxf(s, 1e-6f));   // d^{-1/2}
    }
    __syncthreads();

#pragma unroll
    for (int k = 0; k < 4; ++k) {
        int e = e0 + k; int i = e >> 6, j = e & 63;
        float v = (sy[i] * sA[e]) * sy[j];
        sB[e] = v + ((i == j) ? 1.f : 0.f);        // final A
    }
    __syncthreads();

    // A2 = A @ A into sA (scratch), emit A
#pragma unroll
    for (int k = 0; k < 4; ++k) {
        int e = e0 + k;
        if (outA) outA[e] = sB[e];
        int i = e >> 6, j = e & 63;
        float acc = 0.f;
        for (int q = 0; q < CC; ++q) acc += sB[i * CC + q] * sB[q * CC + j];
        sA[e] = acc;
    }
    __syncthreads();

    // Pack A2 into bf16 hi/lo mma fragments:
    // word w: reg = w&3, lane = (w>>2)&31, ks = (w>>7)&3, mt = w>>9
    // c = mt*16 + (lane>>2) + (reg&1)*8 ; k = ks*16 + 2*(lane&3) + (reg>>1)*8
    for (int w = tid; w < 4 * 4 * 32 * 4; w += 1024) {
        int reg = w & 3, lane = (w >> 2) & 31, ks = (w >> 7) & 3, mt = w >> 9;
        int c = mt * 16 + (lane >> 2) + (reg & 1) * 8;
        int k = ks * 16 + 2 * (lane & 3) + ((reg >> 1) & 1) * 8;
        float v0 = sA[c * 64 + k], v1 = sA[c * 64 + k + 1];
        __nv_bfloat16 h0 = __float2bfloat16(v0), h1 = __float2bfloat16(v1);
        __nv_bfloat16 l0 = __float2bfloat16(v0 - __bfloat162float(h0));
        __nv_bfloat16 l1 = __float2bfloat16(v1 - __bfloat162float(h1));
        g_A2fh[w] = (uint32_t)__bfloat16_as_ushort(h0) |
                    ((uint32_t)__bfloat16_as_ushort(h1) << 16);
        g_A2fl[w] = (uint32_t)__bfloat16_as_ushort(l0) |
                    ((uint32_t)__bfloat16_as_ushort(l1) << 16);
    }
}

// ================== mma.sync bf16 helpers (sm_80+ PTX, compute_103-safe) ====
__device__ __forceinline__ uint32_t smem_u32(const void* p) {
    uint32_t a;
    asm("{ .reg .u64 t; cvta.to.shared.u64 t, %1; cvt.u32.u64 %0, t; }"
        : "=r"(a) : "l"(p));
    return a;
}

__device__ __forceinline__ void ldsm_x4_t(uint32_t& d0, uint32_t& d1,
                                          uint32_t& d2, uint32_t& d3,
                                          uint32_t addr) {
    asm volatile(
        "ldmatrix.sync.aligned.m8n8.x4.trans.shared.b16 {%0,%1,%2,%3}, [%4];"
        : "=r"(d0), "=r"(d1), "=r"(d2), "=r"(d3) : "r"(addr));
}

__device__ __forceinline__ void mma_bf16(float& d0, float& d1, float& d2, float& d3,
                                         uint32_t a0, uint32_t a1, uint32_t a2, uint32_t a3,
                                         uint32_t b0, uint32_t b1) {
    asm volatile(
        "mma.sync.aligned.m16n8k16.row.col.f32.bf16.bf16.f32 "
        "{%0,%1,%2,%3}, {%4,%5,%6,%7}, {%8,%9}, {%0,%1,%2,%3};"
        : "+f"(d0), "+f"(d1), "+f"(d2), "+f"(d3)
        : "r"(a0), "r"(a1), "r"(a2), "r"(a3), "r"(b0), "r"(b1));
}

__device__ __forceinline__ uint32_t pack2h(__nv_bfloat16 a, __nv_bfloat16 b) {
    return (uint32_t)__bfloat16_as_ushort(a) |
           ((uint32_t)__bfloat16_as_ushort(b) << 16);
}

// xt tile: [j=0..63][t=0..127] bf16, row = 256B, 16B-chunk XOR swizzle
__device__ __forceinline__ uint32_t xt_off(int j, int t) {
    return (uint32_t)(j * 256 + ((((t >> 3) ^ (j & 7))) << 4) + (t & 7) * 2);
}

// ---------------- Kernel D: out[b,c,w*T+t] = sum_j A2[c,j] * x[b,w,j,t] ----
// bf16-split mma.sync, warp tile 32c x 32t (2 c-groups x 4 t-groups).
__global__ __launch_bounds__(256, 2) void k_prop_mma(const float* __restrict__ x,
                                                     float* __restrict__ out) {
    __shared__ __nv_bfloat16 xt[2][64 * 128];   // [0]=hi, [1]=lo (16KB each)
    int tid = threadIdx.x;
    int wid = tid >> 5, lane = tid & 31;
    int bw  = blockIdx.y;               // 0..1023
    int tch = blockIdx.x;               // 0..7 (128-wide t chunks)
    int b = bw >> 4, wwin = bw & 15;

    uint32_t sb_hi = smem_u32(&xt[0][0]);
    uint32_t sb_lo = smem_u32(&xt[1][0]);

    // ---- convert x tile -> bf16 hi/lo into swizzled smem ----
#pragma unroll
    for (int r = 0; r < 8; ++r) {
        int lin = tid + r * 256;          // 0..2047 float4 slots (64 j x 32)
        int j = lin >> 5, q = lin & 31;   // t = 4q
        float4 v = reinterpret_cast<const float4*>(x)[
            (((size_t)bw * CC + j) * TT + (size_t)tch * 128) / 4 + q];
        __nv_bfloat16 h0 = __float2bfloat16(v.x), h1 = __float2bfloat16(v.y);
        __nv_bfloat16 h2 = __float2bfloat16(v.z), h3 = __float2bfloat16(v.w);
        __nv_bfloat16 l0 = __float2bfloat16(v.x - __bfloat162float(h0));
        __nv_bfloat16 l1 = __float2bfloat16(v.y - __bfloat162float(h1));
        __nv_bfloat16 l2 = __float2bfloat16(v.z - __bfloat162float(h2));
        __nv_bfloat16 l3 = __float2bfloat16(v.w - __bfloat162float(h3));
        uint32_t off = xt_off(j, 4 * q);
        *reinterpret_cast<uint2*>((char*)xt + off) =
            make_uint2(pack2h(h0, h1), pack2h(h2, h3));
        *reinterpret_cast<uint2*>((char*)xt + 16384 + off) =
            make_uint2(pack2h(l0, l1), pack2h(l2, l3));
    }
    __syncthreads();

    int cg = wid & 1;                 // c half: c0 = cg*32 (2 m16-tiles)
    int tg = wid >> 1;                // t quarter: t0 = tg*32 (4 n8-tiles)
    int c0 = cg * 32, t0 = tg * 32;
    int r = lane >> 2, cq = lane & 3;
    int lm = lane >> 3, li = lane & 7;

    float acc[2][4][4];
#pragma unroll
    for (int m = 0; m < 2; ++m)
#pragma unroll
        for (int n = 0; n < 4; ++n)
#pragma unroll
            for (int i = 0; i < 4; ++i) acc[m][n][i] = 0.f;

    const uint4* fh = reinterpret_cast<const uint4*>(g_A2fh);
    const uint4* fl = reinterpret_cast<const uint4*>(g_A2fl);

#pragma unroll
    for (int ks = 0; ks < 4; ++ks) {
        // A fragments: coalesced LDG.128 of pre-arranged frags
        uint4 ah0 = fh[((cg * 2 + 0) * 4 + ks) * 32 + lane];
        uint4 ah1 = fh[((cg * 2 + 1) * 4 + ks) * 32 + lane];
        uint4 al0 = fl[((cg * 2 + 0) * 4 + ks) * 32 + lane];
        uint4 al1 = fl[((cg * 2 + 1) * 4 + ks) * 32 + lane];

        int kbase = ks * 16 + ((lm & 1) ? 8 : 0) + li;
        uint32_t Bf[2][4];
#pragma unroll
        for (int p = 0; p < 2; ++p) {
            int nb = t0 + p * 16 + ((lm & 2) ? 8 : 0);
            ldsm_x4_t(Bf[p][0], Bf[p][1], Bf[p][2], Bf[p][3],
                      sb_hi + xt_off(kbase, nb));
        }
#pragma unroll
        for (int p = 0; p < 2; ++p) {
            int n0 = 2 * p, n1 = 2 * p + 1;
            mma_bf16(acc[0][n0][0], acc[0][n0][1], acc[0][n0][2], acc[0][n0][3],
                     ah0.x, ah0.y, ah0.z, ah0.w, Bf[p][0], Bf[p][1]);
            mma_bf16(acc[0][n1][0], acc[0][n1][1], acc[0][n1][2], acc[0][n1][3],
                     ah0.x, ah0.y, ah0.z, ah0.w, Bf[p][2], Bf[p][3]);
            mma_bf16(acc[1][n0][0], acc[1][n0][1], acc[1][n0][2], acc[1][n0][3],
                     ah1.x, ah1.y, ah1.z, ah1.w, Bf[p][0], Bf[p][1]);
            mma_bf16(acc[1][n1][0], acc[1][n1][1], acc[1][n1][2], acc[1][n1][3],
                     ah1.x, ah1.y, ah1.z, ah1.w, Bf[p][2], Bf[p][3]);
            mma_bf16(acc[0][n0][0], acc[0][n0][1], acc[0][n0][2], acc[0][n0][3],
                     al0.x, al0.y, al0.z, al0.w, Bf[p][0], Bf[p][1]);
            mma_bf16(acc[0][n1][0], acc[0][n1][1], acc[0][n1][2], acc[0][n1][3],
                     al0.x, al0.y, al0.z, al0.w, Bf[p][2], Bf[p][3]);
            mma_bf16(acc[1][n0][0], acc[1][n0][1], acc[1][n0][2], acc[1][n0][3],
                     al1.x, al1.y, al1.z, al1.w, Bf[p][0], Bf[p][1]);
            mma_bf16(acc[1][n1][0], acc[1][n1][1], acc[1][n1][2], acc[1][n1][3],
                     al1.x, al1.y, al1.z, al1.w, Bf[p][2], Bf[p][3]);
        }
        // lo B (x_lo) with Ah
#pragma unroll
        for (int p = 0; p < 2; ++p) {
            int nb = t0 + p * 16 + ((lm & 2) ? 8 : 0);
            ldsm_x4_t(Bf[p][0], Bf[p][1], Bf[p][2], Bf[p][3],
                      sb_lo + xt_off(kbase, nb));
        }
#pragma unroll
        for (int p = 0; p < 2; ++p) {
            int n0 = 2 * p, n1 = 2 * p + 1;
            mma_bf16(acc[0][n0][0], acc[0][n0][1], acc[0][n0][2], acc[0][n0][3],
                     ah0.x, ah0.y, ah0.z, ah0.w, Bf[p][0], Bf[p][1]);
            mma_bf16(acc[0][n1][0], acc[0][n1][1], acc[0][n1][2], acc[0][n1][3],
                     ah0.x, ah0.y, ah0.z, ah0.w, Bf[p][2], Bf[p][3]);
            mma_bf16(acc[1][n0][0], acc[1][n0][1], acc[1][n0][2], acc[1][n0][3],
                     ah1.x, ah1.y, ah1.z, ah1.w, Bf[p][0], Bf[p][1]);
            mma_bf16(acc[1][n1][0], acc[1][n1][1], acc[1][n1][2], acc[1][n1][3],
                     ah1.x, ah1.y, ah1.z, ah1.w, Bf[p][2], Bf[p][3]);
        }
    }

    // ---- epilogue: direct float2 stores ----
    size_t base = (size_t)b * CC * WT + (size_t)wwin * TT + (size_t)tch * 128 + t0;
#pragma unroll
    for (int m = 0; m < 2; ++m) {
        int cr = c0 + m * 16 + r;
#pragma unroll
        for (int n = 0; n < 4; ++n) {
            int t = n * 8 + 2 * cq;
            *reinterpret_cast<float2*>(out + base + (size_t)cr * WT + t) =
                make_float2(acc[m][n][0], acc[m][n][1]);
            *reinterpret_cast<float2*>(out + base + (size_t)(cr + 8) * WT + t) =
                make_float2(acc[m][n][2], acc[m][n][3]);
        }
    }
}

// ---------------- launch ----------------
extern "C" void kernel_launch(void* const* d_in, const int* in_sizes, int n_in,
                              void* d_out, int out_size) {
    const float* x     = (const float*)d_in[0];
    const float* Wp    = (const float*)d_in[1];
    const float* w1    = (const float*)d_in[2];
    const float* b1    = (const float*)d_in[3];
    const float* w2    = (const float*)d_in[4];
    const float* b2    = (const float*)d_in[5];
    const float* beta  = (const float*)d_in[6];
    const float* gamma = (const float*)d_in[7];
    const float* temp  = (const float*)d_in[8];
    float* out = (float*)d_out;
    float* outA = ((size_t)out_size >= XR_SIZE + CC * CC) ? out + XR_SIZE : nullptr;

    k_stats<<<(BW * CC) / 8, 256>>>(x);
    k_Z<<<dim3(CC, 4), 256>>>(Wp);
    k_graph<<<1, 1024>>>(w1, b1, w2, b2, beta, gamma, temp, outA);
    dim3 g(8, BW);
    k_prop_mma<<<g, 256>>>(x, out);
}

// round 16
// speedup vs baseline: 1.9322x; 1.0541x over previous
#include <cuda_runtime.h>
#include <cuda_bf16.h>
#include <cstdint>
#include <cstddef>

#define BB 64
#define WW 16
#define CC 64
#define TT 1024
#define DE 64
#define BW (BB*WW)           // 1024
#define WT (WW*TT)           // 16384
#define XR_SIZE ((size_t)BB*CC*WT)  // 67108864

__device__ float g_stat[BW*CC];
__device__ float g_Zpart[4][CC*DE];
// A2 pre-arranged as mma fragments: [mt(4)][ks(4)][lane(32)][reg(4)] uint32(bf16x2)
__device__ uint32_t g_A2fh[4*4*32*4];
__device__ uint32_t g_A2fl[4*4*32*4];

// ---------------- Kernel A: per-(b,w,c) robust stats ----------------
__global__ void k_stats(const float* __restrict__ x) {
    int row  = blockIdx.x * 8 + (threadIdx.x >> 5);   // 0..65535
    int lane = threadIdx.x & 31;
    const float4* xv = reinterpret_cast<const float4*>(x + (size_t)row * TT);
    float s1 = 0.f, s2 = 0.f;
#pragma unroll
    for (int i = 0; i < 8; ++i) {
        float4 v = xv[lane + i * 32];
        s1 += v.x + v.y + v.z + v.w;
        s2 += v.x*v.x + v.y*v.y + v.z*v.z + v.w*v.w;
    }
#pragma unroll
    for (int off = 16; off; off >>= 1) {
        s1 += __shfl_down_sync(0xffffffffu, s1, off);
        s2 += __shfl_down_sync(0xffffffffu, s2, off);
    }
    if (lane == 0) g_stat[row] = (s1 + s2) * (0.5f / TT);
}

// ---------------- Kernel B: partial Z over i-quarters ----------------
__global__ void k_Z(const float* __restrict__ Wp) {
    __shared__ float sstat[256];
    __shared__ float part[4][DE];
    int c = blockIdx.x;
    int pr = blockIdx.y;
    int base = pr * 256;
    sstat[threadIdx.x] = g_stat[(base + threadIdx.x) * CC + c];
    __syncthreads();
    int d = threadIdx.x & 63;
    int p = threadIdx.x >> 6;
    float w = Wp[d];
    float acc = 0.f;
    int i0 = p * 64;
    for (int i = i0; i < i0 + 64; ++i) acc += tanhf(sstat[i] * w);
    part[p][d] = acc;
    __syncthreads();
    if (threadIdx.x < DE) {
        g_Zpart[pr][c * DE + threadIdx.x] =
            part[0][threadIdx.x] + part[1][threadIdx.x] +
            part[2][threadIdx.x] + part[3][threadIdx.x];
    }
}

// ---------------- threefry2x32 (JAX partitionable) + gumbel ----------------
__device__ __forceinline__ uint32_t rotl32(uint32_t v, int d) {
    return (v << d) | (v >> (32 - d));
}

__device__ __forceinline__ void threefry_0_42(uint32_t x0, uint32_t x1,
                                              uint32_t& o0, uint32_t& o1) {
    const uint32_t k0 = 0u, k1 = 42u, k2 = 0u ^ 42u ^ 0x1BD11BDAu;
    x0 += k0; x1 += k1;
#define TF_R(r) { x0 += x1; x1 = rotl32(x1, r); x1 ^= x0; }
    TF_R(13) TF_R(15) TF_R(26) TF_R(6)   x0 += k1; x1 += k2 + 1u;
    TF_R(17) TF_R(29) TF_R(16) TF_R(24)  x0 += k2; x1 += k0 + 2u;
    TF_R(13) TF_R(15) TF_R(26) TF_R(6)   x0 += k0; x1 += k1 + 3u;
    TF_R(17) TF_R(29) TF_R(16) TF_R(24)  x0 += k1; x1 += k2 + 4u;
    TF_R(13) TF_R(15) TF_R(26) TF_R(6)   x0 += k2; x1 += k0 + 5u;
#undef TF_R
    o0 = x0; o1 = x1;
}

__device__ __forceinline__ float gumbel_at(int n) {
    uint32_t b0, b1;
    threefry_0_42(0u, (uint32_t)n, b0, b1);
    uint32_t bits = b0 ^ b1;
    float u = __uint_as_float((bits >> 9) | 0x3f800000u) - 1.0f;
    const float tiny = 1.17549435e-38f;
    float v = fmaxf(u, tiny);
    return -logf(-logf(v));
}

// ---------------- Kernel C: graph construction (single block, 1024 thr) ----------------
__global__ __launch_bounds__(1024, 1)
void k_graph(const float* __restrict__ w1, const float* __restrict__ b1,
             const float* __restrict__ w2, const float* __restrict__ b2,
             const float* __restrict__ beta_p, const float* __restrict__ gamma_p,
             const float* __restrict__ temp_p, float* __restrict__ outA) {
    __shared__ float sZ[CC * DE];
    __shared__ float sA[CC * CC];
    __shared__ float sB[CC * CC];
    __shared__ float sy[CC * 68];          // padded rows: conflict-free scan
    __shared__ float sw1[16], sb1[16], sw2[16];
    __shared__ float sconst[4];            // b2, beta, gamma, invT
    int tid = threadIdx.x;

    if (tid < 16) {
        sw1[tid] = w1[tid];
        sb1[tid] = b1[tid];
        sw2[tid] = w2[tid];
    } else if (tid < 20) {
        if (tid == 16) sconst[0] = b2[0];
        if (tid == 17) sconst[1] = beta_p[0];
        if (tid == 18) sconst[2] = gamma_p[0];
        if (tid == 19) sconst[3] = 1.0f / fmaxf(temp_p[0], 1e-6f);
    }

    for (int i = tid; i < CC * DE; i += 1024)
        sZ[i] = (g_Zpart[0][i] + g_Zpart[1][i] + g_Zpart[2][i] + g_Zpart[3][i])
                * (1.0f / BW);
    __syncthreads();

    if (tid < CC) {
        float s = 0.f;
        for (int d = 0; d < DE; ++d) { float z = sZ[tid * DE + d]; s += z * z; }
        sB[tid] = s;  // sq
    }
    __syncthreads();

    float d2r[4];
    int e0 = tid * 4;
    int irow = tid >> 4, jq = (tid & 15) * 4;
#pragma unroll
    for (int k = 0; k < 4; ++k) {
        int e = e0 + k; int i = e >> 6, j = e & 63;
        float dot = 0.f;
        for (int d = 0; d < DE; ++d) dot += sZ[i * DE + d] * sZ[j * DE + d];
        float v = sB[i] + sB[j] - 2.0f * dot;
        d2r[k] = fmaxf(v, 0.f) * 0.5f;
        sA[e] = (i == j) ? 1.f : 0.f;
    }
    __syncthreads();

    const float inv_sqrt2 = 0.70710678118654752440f;

    for (int s = 0; s < 2; ++s) {
        float lb2 = sconst[0], beta = sconst[1], gamma = sconst[2];
#pragma unroll
        for (int k = 0; k < 4; ++k) {
            int e = e0 + k;
            float a = sA[e] - 0.2f * d2r[k];
            float acc = lb2;
#pragma unroll
            for (int h = 0; h < 16; ++h) {
                float z = a * sw1[h] + sb1[h];
                float gel = 0.5f * z * (1.0f + erff(z * inv_sqrt2));
                acc += gel * sw2[h];
            }
            float delta = fmaxf(acc, 0.f) + log1pf(expf(-fabsf(acc)));
            sB[e] = a + beta * (delta * gamma);
        }
        __syncthreads();
#pragma unroll
        for (int k = 0; k < 4; ++k) {
            int e = e0 + k; int i = e >> 6, j = e & 63;
            float v = 0.5f * (sB[e] + sB[j * CC + i]);
            sA[e] = fmaxf(v, 0.f) + ((i == j) ? 1.f : 0.f);
        }
        __syncthreads();
    }

    // ---- Gumbel top-k via parallel rank counting ----
    {
        float invT = sconst[3];
        float yl[4];
#pragma unroll
        for (int jj = 0; jj < 4; ++jj) {
            int j = jq + jj;
            float y = (sA[irow * 64 + j] + gumbel_at(irow * 64 + j)) * invT;
            yl[jj] = y;
            sy[irow * 68 + j] = y;
        }
        __syncthreads();
        int rank[4];
#pragma unroll
        for (int jj = 0; jj < 4; ++jj) rank[jj] = 0;
        for (int k = 0; k < 64; ++k) {
            float yk = sy[irow * 68 + k];
#pragma unroll
            for (int jj = 0; jj < 4; ++jj) {
                int j = jq + jj;
                rank[jj] += (yk > yl[jj]) || (yk == yl[jj] && k < j);
            }
        }
#pragma unroll
        for (int jj = 0; jj < 4; ++jj) {
            int j = jq + jj;
            sB[irow * 64 + j] = (rank[jj] < 16) ? sA[irow * 64 + j] : 0.f;
        }
    }
    __syncthreads();

#pragma unroll
    for (int k = 0; k < 4; ++k) {
        int e = e0 + k; int i = e >> 6, j = e & 63;
        float v = 0.5f * (sB[e] + sB[j * CC + i]);
        sA[e] = fmaxf(v, 0.f) + ((i == j) ? 1.f : 0.f);
    }
    __syncthreads();

    if (tid < CC) {
        float s = 0.f;
        for (int j = 0; j < CC; ++j) s += sA[tid * CC + j];
        sy[tid] = 1.0f / sqrtf(fmaxf(s, 1e-6f));   // d^{-1/2}
    }
    __syncthreads();

#pragma unroll
    for (int k = 0; k < 4; ++k) {
        int e = e0 + k; int i = e >> 6, j = e & 63;
        float v = (sy[i] * sA[e]) * sy[j];
        sB[e] = v + ((i == j) ? 1.f : 0.f);        // final A
    }
    __syncthreads();

    // A2 = A @ A into sA (scratch), emit A
#pragma unroll
    for (int k = 0; k < 4; ++k) {
        int e = e0 + k;
        if (outA) outA[e] = sB[e];
        int i = e >> 6, j = e & 63;
        float acc = 0.f;
        for (int q = 0; q < CC; ++q) acc += sB[i * CC + q] * sB[q * CC + j];
        sA[e] = acc;
    }
    __syncthreads();

    // Pack A2 into bf16 hi/lo mma fragments
    for (int w = tid; w < 4 * 4 * 32 * 4; w += 1024) {
        int reg = w & 3, lane = (w >> 2) & 31, ks = (w >> 7) & 3, mt = w >> 9;
        int c = mt * 16 + (lane >> 2) + (reg & 1) * 8;
        int k = ks * 16 + 2 * (lane & 3) + ((reg >> 1) & 1) * 8;
        float v0 = sA[c * 64 + k], v1 = sA[c * 64 + k + 1];
        __nv_bfloat16 h0 = __float2bfloat16(v0), h1 = __float2bfloat16(v1);
        __nv_bfloat16 l0 = __float2bfloat16(v0 - __bfloat162float(h0));
        __nv_bfloat16 l1 = __float2bfloat16(v1 - __bfloat162float(h1));
        g_A2fh[w] = (uint32_t)__bfloat16_as_ushort(h0) |
                    ((uint32_t)__bfloat16_as_ushort(h1) << 16);
        g_A2fl[w] = (uint32_t)__bfloat16_as_ushort(l0) |
                    ((uint32_t)__bfloat16_as_ushort(l1) << 16);
    }
}

// ================== mma.sync bf16 helpers (sm_80+ PTX, compute_103-safe) ====
__device__ __forceinline__ uint32_t smem_u32(const void* p) {
    uint32_t a;
    asm("{ .reg .u64 t; cvta.to.shared.u64 t, %1; cvt.u32.u64 %0, t; }"
        : "=r"(a) : "l"(p));
    return a;
}

__device__ __forceinline__ void ldsm_x4_t(uint32_t& d0, uint32_t& d1,
                                          uint32_t& d2, uint32_t& d3,
                                          uint32_t addr) {
    asm volatile(
        "ldmatrix.sync.aligned.m8n8.x4.trans.shared.b16 {%0,%1,%2,%3}, [%4];"
        : "=r"(d0), "=r"(d1), "=r"(d2), "=r"(d3) : "r"(addr));
}

__device__ __forceinline__ void mma_bf16(float& d0, float& d1, float& d2, float& d3,
                                         uint32_t a0, uint32_t a1, uint32_t a2, uint32_t a3,
                                         uint32_t b0, uint32_t b1) {
    asm volatile(
        "mma.sync.aligned.m16n8k16.row.col.f32.bf16.bf16.f32 "
        "{%0,%1,%2,%3}, {%4,%5,%6,%7}, {%8,%9}, {%0,%1,%2,%3};"
        : "+f"(d0), "+f"(d1), "+f"(d2), "+f"(d3)
        : "r"(a0), "r"(a1), "r"(a2), "r"(a3), "r"(b0), "r"(b1));
}

__device__ __forceinline__ uint32_t pack2h(__nv_bfloat16 a, __nv_bfloat16 b) {
    return (uint32_t)__bfloat16_as_ushort(a) |
           ((uint32_t)__bfloat16_as_ushort(b) << 16);
}

// xt tile: [j=0..63][t=0..127] bf16, row = 256B, 16B-chunk XOR swizzle
__device__ __forceinline__ uint32_t xt_off(int j, int t) {
    return (uint32_t)(j * 256 + ((((t >> 3) ^ (j & 7))) << 4) + (t & 7) * 2);
}

// ---------------- Kernel D: out[b,c,w*T+t] = sum_j A2[c,j] * x[b,w,j,t] ----
// bf16-split mma.sync, warp tile 32c x 32t; 3 blocks/SM via register cap.
__global__ __launch_bounds__(256, 3) void k_prop_mma(const float* __restrict__ x,
                                                     float* __restrict__ out) {
    __shared__ __nv_bfloat16 xt[2][64 * 128];   // [0]=hi, [1]=lo (16KB each)
    int tid = threadIdx.x;
    int wid = tid >> 5, lane = tid & 31;
    int bw  = blockIdx.y;               // 0..1023
    int tch = blockIdx.x;               // 0..7 (128-wide t chunks)
    int b = bw >> 4, wwin = bw & 15;

    uint32_t sb_hi = smem_u32(&xt[0][0]);
    uint32_t sb_lo = smem_u32(&xt[1][0]);

    // ---- convert x tile -> bf16 hi/lo into swizzled smem ----
#pragma unroll
    for (int r = 0; r < 8; ++r) {
        int lin = tid + r * 256;          // 0..2047 float4 slots (64 j x 32)
        int j = lin >> 5, q = lin & 31;   // t = 4q
        float4 v = reinterpret_cast<const float4*>(x)[
            (((size_t)bw * CC + j) * TT + (size_t)tch * 128) / 4 + q];
        __nv_bfloat16 h0 = __float2bfloat16(v.x), h1 = __float2bfloat16(v.y);
        __nv_bfloat16 h2 = __float2bfloat16(v.z), h3 = __float2bfloat16(v.w);
        __nv_bfloat16 l0 = __float2bfloat16(v.x - __bfloat162float(h0));
        __nv_bfloat16 l1 = __float2bfloat16(v.y - __bfloat162float(h1));
        __nv_bfloat16 l2 = __float2bfloat16(v.z - __bfloat162float(h2));
        __nv_bfloat16 l3 = __float2bfloat16(v.w - __bfloat162float(h3));
        uint32_t off = xt_off(j, 4 * q);
        *reinterpret_cast<uint2*>((char*)xt + off) =
            make_uint2(pack2h(h0, h1), pack2h(h2, h3));
        *reinterpret_cast<uint2*>((char*)xt + 16384 + off) =
            make_uint2(pack2h(l0, l1), pack2h(l2, l3));
    }
    __syncthreads();

    int cg = wid & 1;                 // c half: c0 = cg*32 (2 m16-tiles)
    int tg = wid >> 1;                // t quarter: t0 = tg*32 (4 n8-tiles)
    int c0 = cg * 32, t0 = tg * 32;
    int r = lane >> 2, cq = lane & 3;
    int lm = lane >> 3, li = lane & 7;

    float acc[2][4][4];
#pragma unroll
    for (int m = 0; m < 2; ++m)
#pragma unroll
        for (int n = 0; n < 4; ++n)
#pragma unroll
            for (int i = 0; i < 4; ++i) acc[m][n][i] = 0.f;

    const uint4* fh = reinterpret_cast<const uint4*>(g_A2fh);
    const uint4* fl = reinterpret_cast<const uint4*>(g_A2fl);

#pragma unroll
    for (int ks = 0; ks < 4; ++ks) {
        // A fragments: coalesced LDG.128 of pre-arranged frags
        uint4 ah0 = fh[((cg * 2 + 0) * 4 + ks) * 32 + lane];
        uint4 ah1 = fh[((cg * 2 + 1) * 4 + ks) * 32 + lane];
        uint4 al0 = fl[((cg * 2 + 0) * 4 + ks) * 32 + lane];
        uint4 al1 = fl[((cg * 2 + 1) * 4 + ks) * 32 + lane];

        int kbase = ks * 16 + ((lm & 1) ? 8 : 0) + li;
        uint32_t Bf[2][4];
#pragma unroll
        for (int p = 0; p < 2; ++p) {
            int nb = t0 + p * 16 + ((lm & 2) ? 8 : 0);
            ldsm_x4_t(Bf[p][0], Bf[p][1], Bf[p][2], Bf[p][3],
                      sb_hi + xt_off(kbase, nb));
        }
#pragma unroll
        for (int p = 0; p < 2; ++p) {
            int n0 = 2 * p, n1 = 2 * p + 1;
            mma_bf16(acc[0][n0][0], acc[0][n0][1], acc[0][n0][2], acc[0][n0][3],
                     ah0.x, ah0.y, ah0.z, ah0.w, Bf[p][0], Bf[p][1]);
            mma_bf16(acc[0][n1][0], acc[0][n1][1], acc[0][n1][2], acc[0][n1][3],
                     ah0.x, ah0.y, ah0.z, ah0.w, Bf[p][2], Bf[p][3]);
            mma_bf16(acc[1][n0][0], acc[1][n0][1], acc[1][n0][2], acc[1][n0][3],
                     ah1.x, ah1.y, ah1.z, ah1.w, Bf[p][0], Bf[p][1]);
            mma_bf16(acc[1][n1][0], acc[1][n1][1], acc[1][n1][2], acc[1][n1][3],
                     ah1.x, ah1.y, ah1.z, ah1.w, Bf[p][2], Bf[p][3]);
            mma_bf16(acc[0][n0][0], acc[0][n0][1], acc[0][n0][2], acc[0][n0][3],
                     al0.x, al0.y, al0.z, al0.w, Bf[p][0], Bf[p][1]);
            mma_bf16(acc[0][n1][0], acc[0][n1][1], acc[0][n1][2], acc[0][n1][3],
                     al0.x, al0.y, al0.z, al0.w, Bf[p][2], Bf[p][3]);
            mma_bf16(acc[1][n0][0], acc[1][n0][1], acc[1][n0][2], acc[1][n0][3],
                     al1.x, al1.y, al1.z, al1.w, Bf[p][0], Bf[p][1]);
            mma_bf16(acc[1][n1][0], acc[1][n1][1], acc[1][n1][2], acc[1][n1][3],
                     al1.x, al1.y, al1.z, al1.w, Bf[p][2], Bf[p][3]);
        }
        // lo B (x_lo) with Ah
#pragma unroll
        for (int p = 0; p < 2; ++p) {
            int nb = t0 + p * 16 + ((lm & 2) ? 8 : 0);
            ldsm_x4_t(Bf[p][0], Bf[p][1], Bf[p][2], Bf[p][3],
                      sb_lo + xt_off(kbase, nb));
        }
#pragma unroll
        for (int p = 0; p < 2; ++p) {
            int n0 = 2 * p, n1 = 2 * p + 1;
            mma_bf16(acc[0][n0][0], acc[0][n0][1], acc[0][n0][2], acc[0][n0][3],
                     ah0.x, ah0.y, ah0.z, ah0.w, Bf[p][0], Bf[p][1]);
            mma_bf16(acc[0][n1][0], acc[0][n1][1], acc[0][n1][2], acc[0][n1][3],
                     ah0.x, ah0.y, ah0.z, ah0.w, Bf[p][2], Bf[p][3]);
            mma_bf16(acc[1][n0][0], acc[1][n0][1], acc[1][n0][2], acc[1][n0][3],
                     ah1.x, ah1.y, ah1.z, ah1.w, Bf[p][0], Bf[p][1]);
            mma_bf16(acc[1][n1][0], acc[1][n1][1], acc[1][n1][2], acc[1][n1][3],
                     ah1.x, ah1.y, ah1.z, ah1.w, Bf[p][2], Bf[p][3]);
        }
    }

    // ---- epilogue: direct float2 stores ----
    size_t base = (size_t)b * CC * WT + (size_t)wwin * TT + (size_t)tch * 128 + t0;
#pragma unroll
    for (int m = 0; m < 2; ++m) {
        int cr = c0 + m * 16 + r;
#pragma unroll
        for (int n = 0; n < 4; ++n) {
            int t = n * 8 + 2 * cq;
            *reinterpret_cast<float2*>(out + base + (size_t)cr * WT + t) =
                make_float2(acc[m][n][0], acc[m][n][1]);
            *reinterpret_cast<float2*>(out + base + (size_t)(cr + 8) * WT + t) =
                make_float2(acc[m][n][2], acc[m][n][3]);
        }
    }
}

// ---------------- launch ----------------
extern "C" void kernel_launch(void* const* d_in, const int* in_sizes, int n_in,
                              void* d_out, int out_size) {
    const float* x     = (const float*)d_in[0];
    const float* Wp    = (const float*)d_in[1];
    const float* w1    = (const float*)d_in[2];
    const float* b1    = (const float*)d_in[3];
    const float* w2    = (const float*)d_in[4];
    const float* b2    = (const float*)d_in[5];
    const float* beta  = (const float*)d_in[6];
    const float* gamma = (const float*)d_in[7];
    const float* temp  = (const float*)d_in[8];
    float* out = (float*)d_out;
    float* outA = ((size_t)out_size >= XR_SIZE + CC * CC) ? out + XR_SIZE : nullptr;

    k_stats<<<(BW * CC) / 8, 256>>>(x);
    k_Z<<<dim3(CC, 4), 256>>>(Wp);
    k_graph<<<1, 1024>>>(w1, b1, w2, b2, beta, gamma, temp, outA);
    dim3 g(8, BW);
    k_prop_mma<<<g, 256>>>(x, out);
}